// round 13
// baseline (speedup 1.0000x reference)
#include <cuda_runtime.h>
#include <math.h>

#define Bq 8
#define Tq 4096
#define Dq 896
#define Sq 64
#define Cq 128
#define NCq 32

#define GM (Bq*Tq)
#define GN Dq
#define GK Dq

// ---------------- global scratch ----------------
__device__ float g_G[Bq][NCq][Cq][Cq];
__device__ float g_Gx[Bq][NCq][Cq][Cq];
__device__ float g_hd[Bq][Tq][4];
__device__ float g_Ball[NCq][Bq][Sq][Dq];
__device__ float g_P0[Bq][Cq][Sq];
__device__ float g_u[Bq][Sq];
__device__ float g_beta[Bq][NCq][Cq][Sq];
__device__ float g_gamma[Bq][NCq][Cq][Cq];
__device__ float g_afinC[NCq][Bq][Sq];
__device__ float g_kapC[NCq][Bq][Cq];
__device__ int   g_idxC[NCq][Bq][Cq];
__device__ unsigned g_mskC[NCq][Bq][Sq][4];
__device__ float g_E[Bq][NCq][Cq][Sq];
__device__ float g_invA[Bq][NCq][Cq];
__device__ float g_wgA[Bq][NCq][Cq];
__device__ int   g_miA[Bq][NCq][Cq];
__device__ float g_m[(size_t)Bq*Tq*Dq];
__device__ float g_stats[(size_t)Bq*Tq][2];

// chunk_kernel scan smem layout (float offsets) — R7 baseline
#define OF_Q    0                  // 128*65 = 8320
#define OF_G    8320               // 16384
#define OF_GX   24704              // 16384
#define OF_HD   41088              // 512
#define OF_A    41600              // 64
#define OF_R    41664              // 128
#define OF_IDX  41792              // 128 (int)
#define OF_MSK  41920              // 256 (uint 64x4)
#define OF_KF   42176              // 128
#define SMEM_FLOATS 42304
#define SMEM_BYTES (SMEM_FLOATS*4)

// recon smem layout
#define RS_E    0
#define RS_A    8192
#define RS_R    16384
#define RS_INV  16512
#define RS_WG   16640
#define RS_MI   16768
#define RSMEM_FLOATS 16896
#define RSMEM_BYTES (RSMEM_FLOATS*4)

__device__ __forceinline__ unsigned okey(float f) {
    unsigned u = __float_as_uint(f);
    return (u & 0x80000000u) ? ~u : (u | 0x80000000u);
}
__device__ __forceinline__ float dekey(unsigned k) {
    unsigned u = (k & 0x80000000u) ? (k ^ 0x80000000u) : ~k;
    return __uint_as_float(u);
}

// ---------------------------------------------------------------------
__global__ void init_kernel() {
    int tid = blockIdx.x * blockDim.x + threadIdx.x;
    int stride = gridDim.x * blockDim.x;
    int nb = Bq * Sq * Dq;
    for (int i = tid; i < nb; i += stride) (&g_Ball[0][0][0][0])[i] = 0.f;
    int np = Bq * Cq * Sq;
    for (int i = tid; i < np; i += stride) (&g_P0[0][0][0])[i] = 0.f;
    if (tid < Bq * Sq) (&g_u[0][0])[tid] = 0.f;
}

// ---------------------------------------------------------------------
__global__ __launch_bounds__(256) void pre_kernel(
    const float* __restrict__ h,
    const float* __restrict__ W_nm,
    const float* __restrict__ W_wg)
{
    __shared__ float As[8][128];
    __shared__ float Bs[8][128];

    const int tid = threadIdx.x;
    const int tr = tid >> 4, tc = tid & 15;
    const int lr = tid >> 1, lk = (tid & 1) * 4;

    int b, c;
    const float *Arow, *Brow;
    float* outp;
    bool doHd;
    if (blockIdx.x < Bq * NCq) {
        b = blockIdx.x / NCq; c = blockIdx.x % NCq;
        Arow = h + ((size_t)b * Tq + c * Cq) * Dq;
        Brow = Arow;
        outp = &g_G[b][c][0][0];
        doHd = true;
    } else {
        int k = blockIdx.x - Bq * NCq;
        b = k / (NCq - 1); c = k % (NCq - 1);
        Arow = h + ((size_t)b * Tq + (c + 1) * Cq) * Dq;
        Brow = h + ((size_t)b * Tq + c * Cq) * Dq;
        outp = &g_Gx[b][c][0][0];
        doHd = false;
    }

    float acc[8][8];
    #pragma unroll
    for (int i = 0; i < 8; ++i)
        #pragma unroll
        for (int j = 0; j < 8; ++j) acc[i][j] = 0.f;

    float4 av = *(const float4*)(Arow + (size_t)lr * Dq + lk);
    float4 bv = *(const float4*)(Brow + (size_t)lr * Dq + lk);
    for (int k0 = 0; k0 < Dq; k0 += 8) {
        __syncthreads();
        As[lk + 0][lr] = av.x; As[lk + 1][lr] = av.y;
        As[lk + 2][lr] = av.z; As[lk + 3][lr] = av.w;
        Bs[lk + 0][lr] = bv.x; Bs[lk + 1][lr] = bv.y;
        Bs[lk + 2][lr] = bv.z; Bs[lk + 3][lr] = bv.w;
        __syncthreads();
        if (k0 + 8 < Dq) {
            av = *(const float4*)(Arow + (size_t)lr * Dq + k0 + 8 + lk);
            bv = *(const float4*)(Brow + (size_t)lr * Dq + k0 + 8 + lk);
        }
        #pragma unroll
        for (int kk = 0; kk < 8; ++kk) {
            float a[8], bb[8];
            #pragma unroll
            for (int i = 0; i < 8; ++i) a[i]  = As[kk][tr + 16 * i];
            #pragma unroll
            for (int j = 0; j < 8; ++j) bb[j] = Bs[kk][tc + 16 * j];
            #pragma unroll
            for (int i = 0; i < 8; ++i)
                #pragma unroll
                for (int j = 0; j < 8; ++j)
                    acc[i][j] = fmaf(a[i], bb[j], acc[i][j]);
        }
    }
    #pragma unroll
    for (int i = 0; i < 8; ++i)
        #pragma unroll
        for (int j = 0; j < 8; ++j)
            outp[(tr + 16 * i) * Cq + tc + 16 * j] = acc[i][j];

    if (doHd) {
        const int w = tid >> 5, l = tid & 31;
        const int t0 = c * Cq;
        for (int r = w; r < Cq; r += 8) {
            const float* hr = Arow + (size_t)r * Dq;
            float s0 = 0.f, s1 = 0.f, s2 = 0.f;
            for (int d = l; d < Dq; d += 32) {
                float x = hr[d];
                s0 += x * W_nm[d];
                s1 += x * W_nm[Dq + d];
                s2 += x * W_wg[d];
            }
            #pragma unroll
            for (int o = 16; o > 0; o >>= 1) {
                s0 += __shfl_xor_sync(0xffffffffu, s0, o);
                s1 += __shfl_xor_sync(0xffffffffu, s1, o);
                s2 += __shfl_xor_sync(0xffffffffu, s2, o);
            }
            if (l == 0) {
                g_hd[b][t0 + r][0] = s0;
                g_hd[b][t0 + r][1] = s1;
                g_hd[b][t0 + r][2] = s2;
                g_hd[b][t0 + r][3] = 0.f;
            }
        }
    }
}

// ---------------------------------------------------------------------
// chunk launch c (R7 baseline):
//   blocks 0..7    : fixup(Q) then minimal scan(c) (records E/inv/wg/mi)
//   blocks 8..135  : build B_c from scan(c-1); P0(c) = H_{c+1}.B_c
// ---------------------------------------------------------------------
__global__ __launch_bounds__(256) void chunk_kernel(
    const float* __restrict__ h, const int* __restrict__ mask,
    const float* __restrict__ b_nm, const float* __restrict__ W_wg,
    const float* __restrict__ b_wg, int c)
{
    extern __shared__ float sm[];
    const int tid = threadIdx.x;

    if (blockIdx.x < 8) {
        float*    Qs   = sm + OF_Q;
        float*    sG   = sm + OF_G;
        float*    sGx  = sm + OF_GX;
        float4*   sHd  = (float4*)(sm + OF_HD);
        float*    Asm  = sm + OF_A;
        float*    rS   = sm + OF_R;
        int*      idxS = (int*)(sm + OF_IDX);
        unsigned* mskS = (unsigned*)(sm + OF_MSK);
        float*    kapF = sm + OF_KF;

        const int b = blockIdx.x;
        const int t0 = c * Cq;

        if (tid < Cq) {
            float4 hv = ((const float4*)g_hd)[(size_t)b * Tq + t0 + tid];
            hv.w = (float)mask[b * Tq + t0 + tid];
            sHd[tid] = hv;
        }
        {
            const float4* gsrc = (const float4*)&g_G[b][c][0][0];
            #pragma unroll 4
            for (int i = tid; i < Cq * Cq / 4; i += 256)
                ((float4*)sG)[i] = gsrc[i];
        }
        if (c > 0) {
            const float4* xsrc = (const float4*)&g_Gx[b][c - 1][0][0];
            #pragma unroll 4
            for (int i = tid; i < Cq * Cq / 4; i += 256)
                ((float4*)sGx)[i] = xsrc[i];
            if (tid < Sq) Asm[tid] = g_afinC[c - 1][b][tid];
            if (tid < Cq) {
                kapF[tid] = g_kapC[c - 1][b][tid];
                idxS[tid] = g_idxC[c - 1][b][tid];
            }
        }
        __syncthreads();

        if (c == 0) {
            for (int i = tid; i < Cq * Sq; i += 256) {
                int tau = i >> 6, s = i & 63;
                Qs[tau * 65 + s] = 0.f;
            }
        } else {
            const int t = tid >> 1, hf = (tid & 1) * 32;
            const float* P0r = &g_P0[b][t][0];
            float* Qr = Qs + t * 65;
            #pragma unroll 8
            for (int q = 0; q < 32; ++q) {
                int s = hf + q;
                Qr[s] = Asm[s] * P0r[s];
            }
            const float* gxr = sGx + t * Cq;
            for (int j = 0; j < Cq; ++j) {
                int s = idxS[j];
                if ((unsigned)(s - hf) < 32u)
                    Qr[s] = fmaf(kapF[j], gxr[j], Qr[s]);
            }
        }
        __syncthreads();
        if (tid < Sq) Asm[tid] = 1.f;
        if (tid < Cq) { rS[tid] = 0.f; idxS[tid] = 0; }
        mskS[tid] = 0;
        __syncthreads();

        if (tid < 32) {
            const int l = tid;
            const float scale = rsqrtf((float)Dq);
            const float wwgg = W_wg[Dq];
            const float bnm = b_nm[0], bwg = b_wg[0];
            float A0 = 1.f, A1 = 1.f;
            float R0 = g_u[b][l], R1 = g_u[b][l + 32];
            float* gE = &g_E[b][c][0][0];
            float* gInv = &g_invA[b][c][0];
            float* gWg  = &g_wgA[b][c][0];
            int*   gMi  = &g_miA[b][c][0];

            for (int t = 0; t < Cq; ++t) {
                const float* gr = sG + t * Cq;
                float g0 = gr[l], g1 = gr[l + 32];
                float g2 = gr[l + 64], g3 = gr[l + 96];

                float s0 = Qs[t * 65 + l] * scale;
                float s1 = Qs[t * 65 + l + 32] * scale;

                unsigned k0 = okey(s0), k1 = okey(s1);
                unsigned kmx = __reduce_max_sync(0xffffffffu, k0 > k1 ? k0 : k1);
                float mx = dekey(kmx);
                unsigned b0 = __ballot_sync(0xffffffffu, k0 == kmx);
                unsigned b1 = __ballot_sync(0xffffffffu, k1 == kmx);
                int mi = b0 ? (__ffs(b0) - 1) : (__ffs(b1) + 31);

                float e0 = __expf(s0 - mx), e1 = __expf(s1 - mx);
                gE[t * Sq + l] = e0;
                gE[t * Sq + l + 32] = e1;

                float pe = e0 + e1;
                float pd = e0 * R0 + e1 * R1;
                #pragma unroll
                for (int o = 16; o > 0; o >>= 1) {
                    pe += __shfl_xor_sync(0xffffffffu, pe, o);
                    pd += __shfl_xor_sync(0xffffffffu, pd, o);
                }
                float inv = __fdividef(1.f, pe);
                float mdot = pd * inv;

                float4 hdt = sHd[t];
                float gg = __fdividef(1.f, 1.f + __expf(-(hdt.x + mdot + bnm)));
                float wg = __fdividef(1.f, 1.f + __expf(-(hdt.z + gg * wwgg + bwg)));
                wg = fminf(wg, 0.2f) * hdt.w;

                if (l == 0) gInv[t] = inv;
                if (l == 1) gWg[t] = wg;
                if (l == 2) gMi[t] = mi;

                float dec = 1.f - wg;
                if (mi == l) {
                    A0 *= dec;
                    R0 = fmaf(dec, R0, wg * hdt.y);
                    Asm[mi] = A0;
                    rS[t] = wg / A0;
                    idxS[t] = mi;
                    mskS[mi * 4 + (t >> 5)] |= 1u << (t & 31);
                } else if (mi == l + 32) {
                    A1 *= dec;
                    R1 = fmaf(dec, R1, wg * hdt.y);
                    Asm[mi] = A1;
                    rS[t] = wg / A1;
                    idxS[t] = mi;
                    mskS[mi * 4 + (t >> 5)] |= 1u << (t & 31);
                }
                {
                    float v;
                    v = Qs[l * 65 + mi];
                    Qs[l * 65 + mi] = fmaf(dec, v, wg * g0);
                    v = Qs[(l + 32) * 65 + mi];
                    Qs[(l + 32) * 65 + mi] = fmaf(dec, v, wg * g1);
                    v = Qs[(l + 64) * 65 + mi];
                    Qs[(l + 64) * 65 + mi] = fmaf(dec, v, wg * g2);
                    v = Qs[(l + 96) * 65 + mi];
                    Qs[(l + 96) * 65 + mi] = fmaf(dec, v, wg * g3);
                }
                __syncwarp();
            }

            g_u[b][l] = R0; g_u[b][l + 32] = R1;
            g_afinC[c][b][l] = A0; g_afinC[c][b][l + 32] = A1;
            #pragma unroll
            for (int q = 0; q < 4; ++q) {
                int j = l + 32 * q;
                int ix = idxS[j];
                g_kapC[c][b][j] = rS[j] * Asm[ix];
                g_idxC[c][b][j] = ix;
            }
        }
        __syncthreads();
        ((unsigned*)&g_mskC[c][b][0][0])[tid] = mskS[tid];
    } else {
        if (c == 0) return;
        const int id = blockIdx.x - 8;
        const int b = id >> 4, s0 = (id & 15) * 4;

        float*    kap2 = sm;
        float*    af4  = sm + 128;
        unsigned* msk4 = (unsigned*)(sm + 132);
        float*    Bsm  = sm + 160;

        if (tid < Cq) kap2[tid] = g_kapC[c - 1][b][tid];
        if (tid < 4)  af4[tid] = g_afinC[c - 1][b][s0 + tid];
        if (tid < 16) msk4[tid] = ((unsigned*)&g_mskC[c - 1][b][s0][0])[tid];
        __syncthreads();

        const float* Hp = h + ((size_t)b * Tq + (c - 1) * Cq) * Dq;
        if (tid < 224) {
            #pragma unroll
            for (int k = 0; k < 4; ++k) {
                const int s = s0 + k;
                float4 v = ((const float4*)&g_Ball[c - 1][b][s][0])[tid];
                const float as = af4[k];
                v.x *= as; v.y *= as; v.z *= as; v.w *= as;
                #pragma unroll
                for (int w2 = 0; w2 < 4; ++w2) {
                    unsigned wd = msk4[k * 4 + w2];
                    while (wd) {
                        int bp = __ffs(wd) - 1; wd &= wd - 1;
                        int j = w2 * 32 + bp;
                        float kj = kap2[j];
                        float4 hv = ((const float4*)(Hp + (size_t)j * Dq))[tid];
                        v.x = fmaf(kj, hv.x, v.x); v.y = fmaf(kj, hv.y, v.y);
                        v.z = fmaf(kj, hv.z, v.z); v.w = fmaf(kj, hv.w, v.w);
                    }
                }
                ((float4*)&g_Ball[c][b][s][0])[tid] = v;
                ((float4*)&Bsm[k * Dq])[tid] = v;
            }
        }
        __syncthreads();

        if (c < NCq - 1) {
            const int t = tid >> 1, sp = (tid & 1) * 2;
            const float4* Hn = (const float4*)(h + ((size_t)b * Tq + (c + 1) * Cq + t) * Dq);
            const float4* Ba = (const float4*)&Bsm[(sp + 0) * Dq];
            const float4* Bb = (const float4*)&Bsm[(sp + 1) * Dq];
            float a0 = 0.f, a1 = 0.f;
            #pragma unroll 4
            for (int k = 0; k < Dq / 4; ++k) {
                float4 hv = Hn[k];
                float4 x = Ba[k];
                a0 += hv.x * x.x + hv.y * x.y + hv.z * x.z + hv.w * x.w;
                float4 y = Bb[k];
                a1 += hv.x * y.x + hv.y * y.y + hv.z * y.z + hv.w * y.w;
            }
            g_P0[b][t][s0 + sp + 0] = a0;
            g_P0[b][t][s0 + sp + 1] = a1;
        }
    }
}

// ---------------------------------------------------------------------
// recon(c): rebuild beta/gamma for chunk c (grid = 8, one block per b)
// ---------------------------------------------------------------------
__global__ __launch_bounds__(256) void recon_kernel(int c) {
    extern __shared__ float rs[];
    float* sE   = rs + RS_E;
    float* sA   = rs + RS_A;
    float* sr   = rs + RS_R;
    float* sinv = rs + RS_INV;
    float* swg  = rs + RS_WG;
    int*   smi  = (int*)(rs + RS_MI);

    const int b = blockIdx.x;
    const int tid = threadIdx.x;

    const float4* esrc = (const float4*)&g_E[b][c][0][0];
    #pragma unroll 4
    for (int i = tid; i < Cq * Sq / 4; i += 256) ((float4*)sE)[i] = esrc[i];
    if (tid < Cq) {
        sinv[tid] = g_invA[b][c][tid];
        swg[tid]  = g_wgA[b][c][tid];
        smi[tid]  = g_miA[b][c][tid];
    }
    __syncthreads();

    if (tid < Sq) {
        float A = 1.f;
        for (int t = 0; t < Cq; ++t) {
            sA[t * Sq + tid] = A;
            if (smi[t] == tid) {
                A *= (1.f - swg[t]);
                sr[t] = swg[t] / A;
            }
        }
    }
    __syncthreads();

    float* bet = &g_beta[b][c][0][0];
    for (int i = tid; i < Cq * Sq; i += 256) {
        int t = i >> 6;
        bet[i] = sE[i] * sinv[t] * sA[i];
    }
    float* gam = &g_gamma[b][c][0][0];
    for (int i = tid; i < Cq * Cq; i += 256) {
        int t = i >> 7, j = i & 127;
        float gv = 0.f;
        if (j < t) {
            int ix = smi[j];
            gv = sE[t * Sq + ix] * sinv[t] * sr[j] * sA[t * Sq + ix];
        }
        gam[i] = gv;
    }
}

// ---------------------------------------------------------------------
// mbuild(c): m = [beta|gamma] @ [B_c ; H_c]  (grid = 56)
// ---------------------------------------------------------------------
__global__ __launch_bounds__(256) void mbuild_kernel(const float* __restrict__ h, int cc)
{
    __shared__ float As2[8][128];
    __shared__ float Bs[8][128];

    const int r  = blockIdx.x;
    const int b  = r / 7;
    const int n0 = (r % 7) * 128;
    const int t0 = cc * Cq;
    const int tid = threadIdx.x;

    const float* Bold = &g_Ball[cc][b][0][0];
    const float* Hc = h + ((size_t)b * Tq + t0) * Dq;
    const float* bet = &g_beta[b][cc][0][0];
    const float* gam = &g_gamma[b][cc][0][0];

    const int tr = tid >> 4, tc = tid & 15;
    const int lr = tid >> 1, lk = (tid & 1) * 4;
    const int kr = tid >> 5, nc = (tid & 31) * 4;

    float acc[8][8];
    #pragma unroll
    for (int i = 0; i < 8; ++i)
        #pragma unroll
        for (int j = 0; j < 8; ++j) acc[i][j] = 0.f;

    for (int k0 = 0; k0 < Sq + Cq; k0 += 8) {
        float4 av = (k0 < Sq)
            ? *(const float4*)(bet + lr * Sq + k0 + lk)
            : *(const float4*)(gam + lr * Cq + k0 - Sq + lk);
        int kg = k0 + kr;
        const float* rp = (kg < Sq) ? (Bold + (size_t)kg * Dq)
                                    : (Hc + (size_t)(kg - Sq) * Dq);
        float4 bv = *(const float4*)(rp + n0 + nc);
        __syncthreads();
        As2[lk + 0][lr] = av.x; As2[lk + 1][lr] = av.y;
        As2[lk + 2][lr] = av.z; As2[lk + 3][lr] = av.w;
        Bs[kr][nc + 0] = bv.x; Bs[kr][nc + 1] = bv.y;
        Bs[kr][nc + 2] = bv.z; Bs[kr][nc + 3] = bv.w;
        __syncthreads();
        #pragma unroll
        for (int kk = 0; kk < 8; ++kk) {
            float a[8], bb[8];
            #pragma unroll
            for (int i = 0; i < 8; ++i) a[i]  = As2[kk][tr + 16 * i];
            #pragma unroll
            for (int j = 0; j < 8; ++j) bb[j] = Bs[kk][tc + 16 * j];
            #pragma unroll
            for (int i = 0; i < 8; ++i)
                #pragma unroll
                for (int j = 0; j < 8; ++j)
                    acc[i][j] = fmaf(a[i], bb[j], acc[i][j]);
        }
    }
    #pragma unroll
    for (int i = 0; i < 8; ++i) {
        size_t row = (size_t)b * Tq + t0 + tr + 16 * i;
        #pragma unroll
        for (int j = 0; j < 8; ++j)
            g_m[row * Dq + n0 + tc + 16 * j] = acc[i][j];
    }
}

// ---------------------------------------------------------------------
// stats(c): LN stats for chunk c's 1024 rows (grid = 16)
// ---------------------------------------------------------------------
__global__ __launch_bounds__(256) void stats_kernel(int cs) {
    const int idx = blockIdx.x;
    const int w = threadIdx.x >> 5, l = threadIdx.x & 31;
    for (int q = 0; q < 8; ++q) {
        int rl = idx * 64 + w * 8 + q;
        int b = rl >> 7, t = rl & 127;
        size_t row = (size_t)b * Tq + cs * Cq + t;
        const float* mr = g_m + row * Dq;
        float s = 0.f, s2 = 0.f;
        for (int d = l; d < Dq; d += 32) {
            float v = mr[d]; s += v; s2 += v * v;
        }
        #pragma unroll
        for (int o = 16; o > 0; o >>= 1) {
            s  += __shfl_xor_sync(0xffffffffu, s, o);
            s2 += __shfl_xor_sync(0xffffffffu, s2, o);
        }
        if (l == 0) {
            float mu = s * (1.f / (float)Dq);
            float var = s2 * (1.f / (float)Dq) - mu * mu;
            g_stats[row][0] = mu;
            g_stats[row][1] = rsqrtf(var + 1e-5f);
        }
    }
}

// ---------------------------------------------------------------------
// gemm(c): out rows of chunk c, 64x128 tiles (grid = 112)
// ---------------------------------------------------------------------
__global__ __launch_bounds__(256) void gemm_kernel(
    const float* __restrict__ Wt, const float* __restrict__ H,
    const float* __restrict__ lng, const float* __restrict__ lnb,
    float* __restrict__ C, int cg)
{
    __shared__ float As2[8][64];
    __shared__ float Bs2[8][128];

    const int idx = blockIdx.x;                // 0..111
    const int bb = idx / 14;
    const int rem = idx % 14;
    const int rowt = rem / 7;
    const int n0 = (rem % 7) * 128;
    const size_t bm = (size_t)bb * Tq + cg * Cq + rowt * 64;
    const int tid = threadIdx.x;

    const int tr = tid >> 4, tc = tid & 15;
    const int lr = tid >> 1, lk = (tid & 1) * 4;
    const int lrA = (tid & 127) >> 1, lkA = (tid & 1) * 4;

    const float* Ap = g_m + (bm + lrA) * GK + lkA;
    const float* Bp = Wt  + (size_t)(n0 + lr) * GK + lk;
    float mu = 0.f, rs = 0.f;
    if (tid < 128) {
        mu = g_stats[bm + lrA][0];
        rs = g_stats[bm + lrA][1];
    }

    float acc[4][8];
    #pragma unroll
    for (int i = 0; i < 4; ++i)
        #pragma unroll
        for (int j = 0; j < 8; ++j) acc[i][j] = 0.f;

    float4 av = make_float4(0.f, 0.f, 0.f, 0.f);
    if (tid < 128) av = *(const float4*)(Ap);
    float4 bv = *(const float4*)(Bp);

    for (int k0 = 0; k0 < GK; k0 += 8) {
        float4 an = make_float4(0.f, 0.f, 0.f, 0.f);
        if (tid < 128) {
            float4 gv = *(const float4*)(lng + k0 + lkA);
            float4 ov = *(const float4*)(lnb + k0 + lkA);
            an.x = (av.x - mu) * rs * gv.x + ov.x;
            an.y = (av.y - mu) * rs * gv.y + ov.y;
            an.z = (av.z - mu) * rs * gv.z + ov.z;
            an.w = (av.w - mu) * rs * gv.w + ov.w;
        }
        __syncthreads();
        if (tid < 128) {
            As2[lkA + 0][lrA] = an.x; As2[lkA + 1][lrA] = an.y;
            As2[lkA + 2][lrA] = an.z; As2[lkA + 3][lrA] = an.w;
        }
        Bs2[lk + 0][lr] = bv.x; Bs2[lk + 1][lr] = bv.y;
        Bs2[lk + 2][lr] = bv.z; Bs2[lk + 3][lr] = bv.w;
        __syncthreads();
        if (k0 + 8 < GK) {
            if (tid < 128) av = *(const float4*)(Ap + k0 + 8);
            bv = *(const float4*)(Bp + k0 + 8);
        }
        #pragma unroll
        for (int kk = 0; kk < 8; ++kk) {
            float a[4], bb2[8];
            #pragma unroll
            for (int i = 0; i < 4; ++i) a[i]   = As2[kk][tr + 16 * i];
            #pragma unroll
            for (int j = 0; j < 8; ++j) bb2[j] = Bs2[kk][tc + 16 * j];
            #pragma unroll
            for (int i = 0; i < 4; ++i)
                #pragma unroll
                for (int j = 0; j < 8; ++j)
                    acc[i][j] = fmaf(a[i], bb2[j], acc[i][j]);
        }
    }

    #pragma unroll
    for (int i = 0; i < 4; ++i) {
        size_t m = bm + tr + 16 * i;
        #pragma unroll
        for (int j = 0; j < 8; ++j) {
            int n = n0 + tc + 16 * j;
            float d2 = fminf(fmaxf(acc[i][j] * 0.5f, -2.f), 2.f);
            C[m * GN + n] = H[m * GN + n] + d2;
        }
    }
}

// ---------------------------------------------------------------------
extern "C" void kernel_launch(void* const* d_in, const int* in_sizes, int n_in,
                              void* d_out, int out_size) {
    const float* h    = (const float*)d_in[0];
    const int*   mask = (const int*)  d_in[1];
    const float* lng  = (const float*)d_in[2];
    const float* lnb  = (const float*)d_in[3];
    const float* Wout = (const float*)d_in[4];
    const float* Wnm  = (const float*)d_in[5];
    const float* bnm  = (const float*)d_in[6];
    const float* Wwg  = (const float*)d_in[7];
    const float* bwg  = (const float*)d_in[8];
    float* out = (float*)d_out;

    cudaFuncSetAttribute(chunk_kernel,
                         cudaFuncAttributeMaxDynamicSharedMemorySize,
                         SMEM_BYTES);
    cudaFuncSetAttribute(recon_kernel,
                         cudaFuncAttributeMaxDynamicSharedMemorySize,
                         RSMEM_BYTES);

    // second stream + events for graph-captured fork/join overlap
    cudaStream_t s2;
    cudaStreamCreateWithFlags(&s2, cudaStreamNonBlocking);
    cudaEvent_t evF, evJ;
    cudaEventCreateWithFlags(&evF, cudaEventDisableTiming);
    cudaEventCreateWithFlags(&evJ, cudaEventDisableTiming);

    init_kernel<<<448, 256>>>();
    pre_kernel<<<Bq * NCq + Bq * (NCq - 1), 256>>>(h, Wnm, Wwg);

    for (int c = 0; c < NCq; ++c) {
        chunk_kernel<<<136, 256, SMEM_BYTES>>>(h, mask, bnm, Wwg, bwg, c);
        // fork: post(c) on s2 depends on chunk(c) completion
        cudaEventRecord(evF, 0);
        cudaStreamWaitEvent(s2, evF, 0);
        recon_kernel<<<8, 256, RSMEM_BYTES, s2>>>(c);
        mbuild_kernel<<<56, 256, 0, s2>>>(h, c);
        stats_kernel<<<16, 256, 0, s2>>>(c);
        gemm_kernel<<<112, 256, 0, s2>>>(Wout, h, lng, lnb, out, c);
    }

    // join: main stream waits for all posts
    cudaEventRecord(evJ, s2);
    cudaStreamWaitEvent(0, evJ, 0);
}

// round 14
// speedup vs baseline: 1.6994x; 1.6994x over previous
#include <cuda_runtime.h>
#include <math.h>

#define Bq 8
#define Tq 4096
#define Dq 896
#define Sq 64
#define Cq 128
#define NCq 32

#define GM (Bq*Tq)
#define GN Dq
#define GK Dq

// ---------------- global scratch ----------------
__device__ float g_G[Bq][NCq][Cq][Cq];
__device__ float g_Gx[Bq][NCq][Cq][Cq];
__device__ float g_hd[Bq][Tq][4];
__device__ float g_Ball[NCq][Bq][Sq][Dq];
__device__ float g_P0[Bq][Cq][Sq];
__device__ float g_u[Bq][Sq];
__device__ float g_beta[Bq][NCq][Cq][Sq];
__device__ float g_gamma[Bq][NCq][Cq][Cq];
__device__ float g_afinC[NCq][Bq][Sq];
__device__ float g_kapC[NCq][Bq][Cq];
__device__ int   g_idxC[NCq][Bq][Cq];
__device__ unsigned g_mskC[NCq][Bq][Sq][4];
__device__ float g_E[Bq][NCq][Cq][Sq];
__device__ float g_invA[Bq][NCq][Cq];
__device__ float g_wgA[Bq][NCq][Cq];
__device__ int   g_miA[Bq][NCq][Cq];
__device__ float g_m[(size_t)Bq*Tq*Dq];
__device__ float g_stats[(size_t)Bq*Tq][2];

// chunk_kernel scan smem layout (float offsets) — R8 baseline
#define OF_Q    0
#define OF_G    8320
#define OF_GX   24704
#define OF_HD   41088
#define OF_A    41600
#define OF_R    41664
#define OF_IDX  41792
#define OF_MSK  41920
#define OF_KF   42176
#define SMEM_FLOATS 42304
#define SMEM_BYTES (SMEM_FLOATS*4)

// recon smem layout
#define RS_E    0
#define RS_A    8192
#define RS_R    16384
#define RS_INV  16512
#define RS_WG   16640
#define RS_MI   16768
#define RSMEM_FLOATS 16896
#define RSMEM_BYTES (RSMEM_FLOATS*4)

__device__ __forceinline__ unsigned okey(float f) {
    unsigned u = __float_as_uint(f);
    return (u & 0x80000000u) ? ~u : (u | 0x80000000u);
}
__device__ __forceinline__ float dekey(unsigned k) {
    unsigned u = (k & 0x80000000u) ? (k ^ 0x80000000u) : ~k;
    return __uint_as_float(u);
}
__device__ __forceinline__ float to_tf32(float v) {
    unsigned r;
    asm("cvt.rna.tf32.f32 %0, %1;" : "=r"(r) : "f"(v));
    return __uint_as_float(r);
}

// ---------------------------------------------------------------------
__global__ void init_kernel() {
    int tid = blockIdx.x * blockDim.x + threadIdx.x;
    int stride = gridDim.x * blockDim.x;
    int nb = Bq * Sq * Dq;
    for (int i = tid; i < nb; i += stride) (&g_Ball[0][0][0][0])[i] = 0.f;
    int np = Bq * Cq * Sq;
    for (int i = tid; i < np; i += stride) (&g_P0[0][0][0])[i] = 0.f;
    if (tid < Bq * Sq) (&g_u[0][0])[tid] = 0.f;
}

// ---------------------------------------------------------------------
__global__ __launch_bounds__(256) void pre_kernel(
    const float* __restrict__ h,
    const float* __restrict__ W_nm,
    const float* __restrict__ W_wg)
{
    __shared__ float As[8][128];
    __shared__ float Bs[8][128];

    const int tid = threadIdx.x;
    const int tr = tid >> 4, tc = tid & 15;
    const int lr = tid >> 1, lk = (tid & 1) * 4;

    int b, c;
    const float *Arow, *Brow;
    float* outp;
    bool doHd;
    if (blockIdx.x < Bq * NCq) {
        b = blockIdx.x / NCq; c = blockIdx.x % NCq;
        Arow = h + ((size_t)b * Tq + c * Cq) * Dq;
        Brow = Arow;
        outp = &g_G[b][c][0][0];
        doHd = true;
    } else {
        int k = blockIdx.x - Bq * NCq;
        b = k / (NCq - 1); c = k % (NCq - 1);
        Arow = h + ((size_t)b * Tq + (c + 1) * Cq) * Dq;
        Brow = h + ((size_t)b * Tq + c * Cq) * Dq;
        outp = &g_Gx[b][c][0][0];
        doHd = false;
    }

    float acc[8][8];
    #pragma unroll
    for (int i = 0; i < 8; ++i)
        #pragma unroll
        for (int j = 0; j < 8; ++j) acc[i][j] = 0.f;

    float4 av = *(const float4*)(Arow + (size_t)lr * Dq + lk);
    float4 bv = *(const float4*)(Brow + (size_t)lr * Dq + lk);
    for (int k0 = 0; k0 < Dq; k0 += 8) {
        __syncthreads();
        As[lk + 0][lr] = av.x; As[lk + 1][lr] = av.y;
        As[lk + 2][lr] = av.z; As[lk + 3][lr] = av.w;
        Bs[lk + 0][lr] = bv.x; Bs[lk + 1][lr] = bv.y;
        Bs[lk + 2][lr] = bv.z; Bs[lk + 3][lr] = bv.w;
        __syncthreads();
        if (k0 + 8 < Dq) {
            av = *(const float4*)(Arow + (size_t)lr * Dq + k0 + 8 + lk);
            bv = *(const float4*)(Brow + (size_t)lr * Dq + k0 + 8 + lk);
        }
        #pragma unroll
        for (int kk = 0; kk < 8; ++kk) {
            float a[8], bb[8];
            #pragma unroll
            for (int i = 0; i < 8; ++i) a[i]  = As[kk][tr + 16 * i];
            #pragma unroll
            for (int j = 0; j < 8; ++j) bb[j] = Bs[kk][tc + 16 * j];
            #pragma unroll
            for (int i = 0; i < 8; ++i)
                #pragma unroll
                for (int j = 0; j < 8; ++j)
                    acc[i][j] = fmaf(a[i], bb[j], acc[i][j]);
        }
    }
    #pragma unroll
    for (int i = 0; i < 8; ++i)
        #pragma unroll
        for (int j = 0; j < 8; ++j)
            outp[(tr + 16 * i) * Cq + tc + 16 * j] = acc[i][j];

    if (doHd) {
        const int w = tid >> 5, l = tid & 31;
        const int t0 = c * Cq;
        for (int r = w; r < Cq; r += 8) {
            const float* hr = Arow + (size_t)r * Dq;
            float s0 = 0.f, s1 = 0.f, s2 = 0.f;
            for (int d = l; d < Dq; d += 32) {
                float x = hr[d];
                s0 += x * W_nm[d];
                s1 += x * W_nm[Dq + d];
                s2 += x * W_wg[d];
            }
            #pragma unroll
            for (int o = 16; o > 0; o >>= 1) {
                s0 += __shfl_xor_sync(0xffffffffu, s0, o);
                s1 += __shfl_xor_sync(0xffffffffu, s1, o);
                s2 += __shfl_xor_sync(0xffffffffu, s2, o);
            }
            if (l == 0) {
                g_hd[b][t0 + r][0] = s0;
                g_hd[b][t0 + r][1] = s1;
                g_hd[b][t0 + r][2] = s2;
                g_hd[b][t0 + r][3] = 0.f;
            }
        }
    }
}

// ---------------------------------------------------------------------
// chunk launch c (R8 baseline, unchanged)
// ---------------------------------------------------------------------
__global__ __launch_bounds__(256) void chunk_kernel(
    const float* __restrict__ h, const int* __restrict__ mask,
    const float* __restrict__ b_nm, const float* __restrict__ W_wg,
    const float* __restrict__ b_wg, int c)
{
    extern __shared__ float sm[];
    const int tid = threadIdx.x;

    if (blockIdx.x < 8) {
        float*    Qs   = sm + OF_Q;
        float*    sG   = sm + OF_G;
        float*    sGx  = sm + OF_GX;
        float4*   sHd  = (float4*)(sm + OF_HD);
        float*    Asm  = sm + OF_A;
        float*    rS   = sm + OF_R;
        int*      idxS = (int*)(sm + OF_IDX);
        unsigned* mskS = (unsigned*)(sm + OF_MSK);
        float*    kapF = sm + OF_KF;

        const int b = blockIdx.x;
        const int t0 = c * Cq;

        if (tid < Cq) {
            float4 hv = ((const float4*)g_hd)[(size_t)b * Tq + t0 + tid];
            hv.w = (float)mask[b * Tq + t0 + tid];
            sHd[tid] = hv;
        }
        {
            const float4* gsrc = (const float4*)&g_G[b][c][0][0];
            #pragma unroll 4
            for (int i = tid; i < Cq * Cq / 4; i += 256)
                ((float4*)sG)[i] = gsrc[i];
        }
        if (c > 0) {
            const float4* xsrc = (const float4*)&g_Gx[b][c - 1][0][0];
            #pragma unroll 4
            for (int i = tid; i < Cq * Cq / 4; i += 256)
                ((float4*)sGx)[i] = xsrc[i];
            if (tid < Sq) Asm[tid] = g_afinC[c - 1][b][tid];
            if (tid < Cq) {
                kapF[tid] = g_kapC[c - 1][b][tid];
                idxS[tid] = g_idxC[c - 1][b][tid];
            }
        }
        __syncthreads();

        if (c == 0) {
            for (int i = tid; i < Cq * Sq; i += 256) {
                int tau = i >> 6, s = i & 63;
                Qs[tau * 65 + s] = 0.f;
            }
        } else {
            const int t = tid >> 1, hf = (tid & 1) * 32;
            const float* P0r = &g_P0[b][t][0];
            float* Qr = Qs + t * 65;
            #pragma unroll 8
            for (int q = 0; q < 32; ++q) {
                int s = hf + q;
                Qr[s] = Asm[s] * P0r[s];
            }
            const float* gxr = sGx + t * Cq;
            for (int j = 0; j < Cq; ++j) {
                int s = idxS[j];
                if ((unsigned)(s - hf) < 32u)
                    Qr[s] = fmaf(kapF[j], gxr[j], Qr[s]);
            }
        }
        __syncthreads();
        if (tid < Sq) Asm[tid] = 1.f;
        if (tid < Cq) { rS[tid] = 0.f; idxS[tid] = 0; }
        mskS[tid] = 0;
        __syncthreads();

        if (tid < 32) {
            const int l = tid;
            const float scale = rsqrtf((float)Dq);
            const float wwgg = W_wg[Dq];
            const float bnm = b_nm[0], bwg = b_wg[0];
            float A0 = 1.f, A1 = 1.f;
            float R0 = g_u[b][l], R1 = g_u[b][l + 32];
            float* gE = &g_E[b][c][0][0];
            float* gInv = &g_invA[b][c][0];
            float* gWg  = &g_wgA[b][c][0];
            int*   gMi  = &g_miA[b][c][0];

            for (int t = 0; t < Cq; ++t) {
                const float* gr = sG + t * Cq;
                float g0 = gr[l], g1 = gr[l + 32];
                float g2 = gr[l + 64], g3 = gr[l + 96];

                float s0 = Qs[t * 65 + l] * scale;
                float s1 = Qs[t * 65 + l + 32] * scale;

                unsigned k0 = okey(s0), k1 = okey(s1);
                unsigned kmx = __reduce_max_sync(0xffffffffu, k0 > k1 ? k0 : k1);
                float mx = dekey(kmx);
                unsigned b0 = __ballot_sync(0xffffffffu, k0 == kmx);
                unsigned b1 = __ballot_sync(0xffffffffu, k1 == kmx);
                int mi = b0 ? (__ffs(b0) - 1) : (__ffs(b1) + 31);

                float e0 = __expf(s0 - mx), e1 = __expf(s1 - mx);
                gE[t * Sq + l] = e0;
                gE[t * Sq + l + 32] = e1;

                float pe = e0 + e1;
                float pd = e0 * R0 + e1 * R1;
                #pragma unroll
                for (int o = 16; o > 0; o >>= 1) {
                    pe += __shfl_xor_sync(0xffffffffu, pe, o);
                    pd += __shfl_xor_sync(0xffffffffu, pd, o);
                }
                float inv = __fdividef(1.f, pe);
                float mdot = pd * inv;

                float4 hdt = sHd[t];
                float gg = __fdividef(1.f, 1.f + __expf(-(hdt.x + mdot + bnm)));
                float wg = __fdividef(1.f, 1.f + __expf(-(hdt.z + gg * wwgg + bwg)));
                wg = fminf(wg, 0.2f) * hdt.w;

                if (l == 0) gInv[t] = inv;
                if (l == 1) gWg[t] = wg;
                if (l == 2) gMi[t] = mi;

                float dec = 1.f - wg;
                if (mi == l) {
                    A0 *= dec;
                    R0 = fmaf(dec, R0, wg * hdt.y);
                    Asm[mi] = A0;
                    rS[t] = wg / A0;
                    idxS[t] = mi;
                    mskS[mi * 4 + (t >> 5)] |= 1u << (t & 31);
                } else if (mi == l + 32) {
                    A1 *= dec;
                    R1 = fmaf(dec, R1, wg * hdt.y);
                    Asm[mi] = A1;
                    rS[t] = wg / A1;
                    idxS[t] = mi;
                    mskS[mi * 4 + (t >> 5)] |= 1u << (t & 31);
                }
                {
                    float v;
                    v = Qs[l * 65 + mi];
                    Qs[l * 65 + mi] = fmaf(dec, v, wg * g0);
                    v = Qs[(l + 32) * 65 + mi];
                    Qs[(l + 32) * 65 + mi] = fmaf(dec, v, wg * g1);
                    v = Qs[(l + 64) * 65 + mi];
                    Qs[(l + 64) * 65 + mi] = fmaf(dec, v, wg * g2);
                    v = Qs[(l + 96) * 65 + mi];
                    Qs[(l + 96) * 65 + mi] = fmaf(dec, v, wg * g3);
                }
                __syncwarp();
            }

            g_u[b][l] = R0; g_u[b][l + 32] = R1;
            g_afinC[c][b][l] = A0; g_afinC[c][b][l + 32] = A1;
            #pragma unroll
            for (int q = 0; q < 4; ++q) {
                int j = l + 32 * q;
                int ix = idxS[j];
                g_kapC[c][b][j] = rS[j] * Asm[ix];
                g_idxC[c][b][j] = ix;
            }
        }
        __syncthreads();
        ((unsigned*)&g_mskC[c][b][0][0])[tid] = mskS[tid];
    } else {
        if (c == 0) return;
        const int id = blockIdx.x - 8;
        const int b = id >> 4, s0 = (id & 15) * 4;

        float*    kap2 = sm;
        float*    af4  = sm + 128;
        unsigned* msk4 = (unsigned*)(sm + 132);
        float*    Bsm  = sm + 160;

        if (tid < Cq) kap2[tid] = g_kapC[c - 1][b][tid];
        if (tid < 4)  af4[tid] = g_afinC[c - 1][b][s0 + tid];
        if (tid < 16) msk4[tid] = ((unsigned*)&g_mskC[c - 1][b][s0][0])[tid];
        __syncthreads();

        const float* Hp = h + ((size_t)b * Tq + (c - 1) * Cq) * Dq;
        if (tid < 224) {
            #pragma unroll
            for (int k = 0; k < 4; ++k) {
                const int s = s0 + k;
                float4 v = ((const float4*)&g_Ball[c - 1][b][s][0])[tid];
                const float as = af4[k];
                v.x *= as; v.y *= as; v.z *= as; v.w *= as;
                #pragma unroll
                for (int w2 = 0; w2 < 4; ++w2) {
                    unsigned wd = msk4[k * 4 + w2];
                    while (wd) {
                        int bp = __ffs(wd) - 1; wd &= wd - 1;
                        int j = w2 * 32 + bp;
                        float kj = kap2[j];
                        float4 hv = ((const float4*)(Hp + (size_t)j * Dq))[tid];
                        v.x = fmaf(kj, hv.x, v.x); v.y = fmaf(kj, hv.y, v.y);
                        v.z = fmaf(kj, hv.z, v.z); v.w = fmaf(kj, hv.w, v.w);
                    }
                }
                ((float4*)&g_Ball[c][b][s][0])[tid] = v;
                ((float4*)&Bsm[k * Dq])[tid] = v;
            }
        }
        __syncthreads();

        if (c < NCq - 1) {
            const int t = tid >> 1, sp = (tid & 1) * 2;
            const float4* Hn = (const float4*)(h + ((size_t)b * Tq + (c + 1) * Cq + t) * Dq);
            const float4* Ba = (const float4*)&Bsm[(sp + 0) * Dq];
            const float4* Bb = (const float4*)&Bsm[(sp + 1) * Dq];
            float a0 = 0.f, a1 = 0.f;
            #pragma unroll 4
            for (int k = 0; k < Dq / 4; ++k) {
                float4 hv = Hn[k];
                float4 x = Ba[k];
                a0 += hv.x * x.x + hv.y * x.y + hv.z * x.z + hv.w * x.w;
                float4 y = Bb[k];
                a1 += hv.x * y.x + hv.y * y.y + hv.z * y.z + hv.w * y.w;
            }
            g_P0[b][t][s0 + sp + 0] = a0;
            g_P0[b][t][s0 + sp + 1] = a1;
        }
    }
}

// ---------------------------------------------------------------------
__global__ __launch_bounds__(256) void recon_kernel() {
    extern __shared__ float rs[];
    float* sE   = rs + RS_E;
    float* sA   = rs + RS_A;
    float* sr   = rs + RS_R;
    float* sinv = rs + RS_INV;
    float* swg  = rs + RS_WG;
    int*   smi  = (int*)(rs + RS_MI);

    const int b = blockIdx.x >> 5;
    const int c = blockIdx.x & 31;
    const int tid = threadIdx.x;

    const float4* esrc = (const float4*)&g_E[b][c][0][0];
    #pragma unroll 4
    for (int i = tid; i < Cq * Sq / 4; i += 256) ((float4*)sE)[i] = esrc[i];
    if (tid < Cq) {
        sinv[tid] = g_invA[b][c][tid];
        swg[tid]  = g_wgA[b][c][tid];
        smi[tid]  = g_miA[b][c][tid];
    }
    __syncthreads();

    if (tid < Sq) {
        float A = 1.f;
        for (int t = 0; t < Cq; ++t) {
            sA[t * Sq + tid] = A;
            if (smi[t] == tid) {
                A *= (1.f - swg[t]);
                sr[t] = swg[t] / A;
            }
        }
    }
    __syncthreads();

    float* bet = &g_beta[b][c][0][0];
    for (int i = tid; i < Cq * Sq; i += 256) {
        int t = i >> 6;
        bet[i] = sE[i] * sinv[t] * sA[i];
    }
    float* gam = &g_gamma[b][c][0][0];
    for (int i = tid; i < Cq * Cq; i += 256) {
        int t = i >> 7, j = i & 127;
        float gv = 0.f;
        if (j < t) {
            int ix = smi[j];
            gv = sE[t * Sq + ix] * sinv[t] * sr[j] * sA[t * Sq + ix];
        }
        gam[i] = gv;
    }
}

// ---------------------------------------------------------------------
__global__ __launch_bounds__(256) void mbuild_kernel(const float* __restrict__ h)
{
    __shared__ float As2[8][128];
    __shared__ float Bs[8][128];

    const int cc = blockIdx.x / 56;
    const int r  = blockIdx.x % 56;
    const int b  = r / 7;
    const int n0 = (r % 7) * 128;
    const int t0 = cc * Cq;
    const int tid = threadIdx.x;

    const float* Bold = &g_Ball[cc][b][0][0];
    const float* Hc = h + ((size_t)b * Tq + t0) * Dq;
    const float* bet = &g_beta[b][cc][0][0];
    const float* gam = &g_gamma[b][cc][0][0];

    const int tr = tid >> 4, tc = tid & 15;
    const int lr = tid >> 1, lk = (tid & 1) * 4;
    const int kr = tid >> 5, nc = (tid & 31) * 4;

    float acc[8][8];
    #pragma unroll
    for (int i = 0; i < 8; ++i)
        #pragma unroll
        for (int j = 0; j < 8; ++j) acc[i][j] = 0.f;

    for (int k0 = 0; k0 < Sq + Cq; k0 += 8) {
        float4 av = (k0 < Sq)
            ? *(const float4*)(bet + lr * Sq + k0 + lk)
            : *(const float4*)(gam + lr * Cq + k0 - Sq + lk);
        int kg = k0 + kr;
        const float* rp = (kg < Sq) ? (Bold + (size_t)kg * Dq)
                                    : (Hc + (size_t)(kg - Sq) * Dq);
        float4 bv = *(const float4*)(rp + n0 + nc);
        __syncthreads();
        As2[lk + 0][lr] = av.x; As2[lk + 1][lr] = av.y;
        As2[lk + 2][lr] = av.z; As2[lk + 3][lr] = av.w;
        Bs[kr][nc + 0] = bv.x; Bs[kr][nc + 1] = bv.y;
        Bs[kr][nc + 2] = bv.z; Bs[kr][nc + 3] = bv.w;
        __syncthreads();
        #pragma unroll
        for (int kk = 0; kk < 8; ++kk) {
            float a[8], bb[8];
            #pragma unroll
            for (int i = 0; i < 8; ++i) a[i]  = As2[kk][tr + 16 * i];
            #pragma unroll
            for (int j = 0; j < 8; ++j) bb[j] = Bs[kk][tc + 16 * j];
            #pragma unroll
            for (int i = 0; i < 8; ++i)
                #pragma unroll
                for (int j = 0; j < 8; ++j)
                    acc[i][j] = fmaf(a[i], bb[j], acc[i][j]);
        }
    }
    #pragma unroll
    for (int i = 0; i < 8; ++i) {
        size_t row = (size_t)b * Tq + t0 + tr + 16 * i;
        #pragma unroll
        for (int j = 0; j < 8; ++j)
            g_m[row * Dq + n0 + tc + 16 * j] = acc[i][j];
    }
}

// ---------------------------------------------------------------------
__global__ __launch_bounds__(256) void stats_kernel() {
    int row = blockIdx.x * 8 + (threadIdx.x >> 5);
    int l = threadIdx.x & 31;
    const float* mr = g_m + (size_t)row * Dq;
    float s = 0.f, s2 = 0.f;
    for (int d = l; d < Dq; d += 32) { float v = mr[d]; s += v; s2 += v * v; }
    #pragma unroll
    for (int o = 16; o > 0; o >>= 1) {
        s  += __shfl_xor_sync(0xffffffffu, s, o);
        s2 += __shfl_xor_sync(0xffffffffu, s2, o);
    }
    if (l == 0) {
        float mu = s * (1.f / (float)Dq);
        float var = s2 * (1.f / (float)Dq) - mu * mu;
        g_stats[row][0] = mu;
        g_stats[row][1] = rsqrtf(var + 1e-5f);
    }
}

// ---------------------------------------------------------------------
// final GEMM: tf32 mma.sync tensor cores, 128x128x16 tiles.
// out = h + clip(0.5 * LN(m) @ W_out^T, +-2); LN fused into A staging.
// ---------------------------------------------------------------------
__global__ __launch_bounds__(256) void gemm_kernel(
    const float* __restrict__ Wt,
    const float* __restrict__ H,
    const float* __restrict__ lng,
    const float* __restrict__ lnb,
    float* __restrict__ C)
{
    __shared__ float As[16][132];
    __shared__ float Bs[16][132];

    const int bm = blockIdx.y * 128;
    const int bn = blockIdx.x * 128;
    const int tid = threadIdx.x;
    const int lane = tid & 31;
    const int warp = tid >> 5;
    const int wm = (warp >> 1) * 32;   // 0,32,64,96
    const int wn = (warp & 1) * 64;    // 0,64
    const int gr = lane >> 2;          // 0..7
    const int gc = lane & 3;           // 0..3

    // loaders: 2 rows per thread per matrix, 4 k-cols each
    const int lr0 = tid >> 2;          // 0..63
    const int kc  = (tid & 3) * 4;     // 0,4,8,12

    const float* Ap0 = g_m + (size_t)(bm + lr0) * GK + kc;
    const float* Ap1 = g_m + (size_t)(bm + lr0 + 64) * GK + kc;
    const float* Bp0 = Wt + (size_t)(bn + lr0) * GK + kc;
    const float* Bp1 = Wt + (size_t)(bn + lr0 + 64) * GK + kc;
    const float mu0 = g_stats[bm + lr0][0],      rs0 = g_stats[bm + lr0][1];
    const float mu1 = g_stats[bm + lr0 + 64][0], rs1 = g_stats[bm + lr0 + 64][1];

    float acc[2][8][4];
    #pragma unroll
    for (int mt = 0; mt < 2; ++mt)
        #pragma unroll
        for (int nt = 0; nt < 8; ++nt)
            #pragma unroll
            for (int q = 0; q < 4; ++q) acc[mt][nt][q] = 0.f;

    float4 pa0 = *(const float4*)(Ap0);
    float4 pa1 = *(const float4*)(Ap1);
    float4 pb0 = *(const float4*)(Bp0);
    float4 pb1 = *(const float4*)(Bp1);

    for (int k0 = 0; k0 < GK; k0 += 16) {
        float4 gv = *(const float4*)(lng + k0 + kc);
        float4 ov = *(const float4*)(lnb + k0 + kc);
        float4 a0 = pa0, a1 = pa1, b0 = pb0, b1 = pb1;
        a0.x = (a0.x - mu0) * rs0 * gv.x + ov.x;
        a0.y = (a0.y - mu0) * rs0 * gv.y + ov.y;
        a0.z = (a0.z - mu0) * rs0 * gv.z + ov.z;
        a0.w = (a0.w - mu0) * rs0 * gv.w + ov.w;
        a1.x = (a1.x - mu1) * rs1 * gv.x + ov.x;
        a1.y = (a1.y - mu1) * rs1 * gv.y + ov.y;
        a1.z = (a1.z - mu1) * rs1 * gv.z + ov.z;
        a1.w = (a1.w - mu1) * rs1 * gv.w + ov.w;
        __syncthreads();
        As[kc + 0][lr0] = to_tf32(a0.x); As[kc + 1][lr0] = to_tf32(a0.y);
        As[kc + 2][lr0] = to_tf32(a0.z); As[kc + 3][lr0] = to_tf32(a0.w);
        As[kc + 0][lr0 + 64] = to_tf32(a1.x); As[kc + 1][lr0 + 64] = to_tf32(a1.y);
        As[kc + 2][lr0 + 64] = to_tf32(a1.z); As[kc + 3][lr0 + 64] = to_tf32(a1.w);
        Bs[kc + 0][lr0] = to_tf32(b0.x); Bs[kc + 1][lr0] = to_tf32(b0.y);
        Bs[kc + 2][lr0] = to_tf32(b0.z); Bs[kc + 3][lr0] = to_tf32(b0.w);
        Bs[kc + 0][lr0 + 64] = to_tf32(b1.x); Bs[kc + 1][lr0 + 64] = to_tf32(b1.y);
        Bs[kc + 2][lr0 + 64] = to_tf32(b1.z); Bs[kc + 3][lr0 + 64] = to_tf32(b1.w);
        __syncthreads();
        if (k0 + 16 < GK) {
            pa0 = *(const float4*)(Ap0 + k0 + 16);
            pa1 = *(const float4*)(Ap1 + k0 + 16);
            pb0 = *(const float4*)(Bp0 + k0 + 16);
            pb1 = *(const float4*)(Bp1 + k0 + 16);
        }
        #pragma unroll
        for (int ks = 0; ks < 16; ks += 8) {
            unsigned afr[2][4];
            #pragma unroll
            for (int mt = 0; mt < 2; ++mt) {
                int row = wm + mt * 16 + gr;
                afr[mt][0] = __float_as_uint(As[ks + gc][row]);
                afr[mt][1] = __float_as_uint(As[ks + gc][row + 8]);
                afr[mt][2] = __float_as_uint(As[ks + gc + 4][row]);
                afr[mt][3] = __float_as_uint(As[ks + gc + 4][row + 8]);
            }
            unsigned bfr[8][2];
            #pragma unroll
            for (int nt = 0; nt < 8; ++nt) {
                int col = wn + nt * 8 + gr;
                bfr[nt][0] = __float_as_uint(Bs[ks + gc][col]);
                bfr[nt][1] = __float_as_uint(Bs[ks + gc + 4][col]);
            }
            #pragma unroll
            for (int mt = 0; mt < 2; ++mt)
                #pragma unroll
                for (int nt = 0; nt < 8; ++nt) {
                    asm volatile(
                        "mma.sync.aligned.m16n8k8.row.col.f32.tf32.tf32.f32 "
                        "{%0,%1,%2,%3}, {%4,%5,%6,%7}, {%8,%9}, {%0,%1,%2,%3};"
                        : "+f"(acc[mt][nt][0]), "+f"(acc[mt][nt][1]),
                          "+f"(acc[mt][nt][2]), "+f"(acc[mt][nt][3])
                        : "r"(afr[mt][0]), "r"(afr[mt][1]),
                          "r"(afr[mt][2]), "r"(afr[mt][3]),
                          "r"(bfr[nt][0]), "r"(bfr[nt][1]));
                }
        }
    }

    // epilogue: D[row][col]: c0=(gr, 2gc), c1=(gr, 2gc+1), c2=(gr+8, ...)
    #pragma unroll
    for (int mt = 0; mt < 2; ++mt) {
        #pragma unroll
        for (int nt = 0; nt < 8; ++nt) {
            size_t r0 = (size_t)bm + wm + mt * 16 + gr;
            size_t r1 = r0 + 8;
            int n = bn + wn + nt * 8 + 2 * gc;
            float d0 = fminf(fmaxf(acc[mt][nt][0] * 0.5f, -2.f), 2.f);
            float d1 = fminf(fmaxf(acc[mt][nt][1] * 0.5f, -2.f), 2.f);
            float d2 = fminf(fmaxf(acc[mt][nt][2] * 0.5f, -2.f), 2.f);
            float d3 = fminf(fmaxf(acc[mt][nt][3] * 0.5f, -2.f), 2.f);
            C[r0 * GN + n]     = H[r0 * GN + n]     + d0;
            C[r0 * GN + n + 1] = H[r0 * GN + n + 1] + d1;
            C[r1 * GN + n]     = H[r1 * GN + n]     + d2;
            C[r1 * GN + n + 1] = H[r1 * GN + n + 1] + d3;
        }
    }
}

// ---------------------------------------------------------------------
extern "C" void kernel_launch(void* const* d_in, const int* in_sizes, int n_in,
                              void* d_out, int out_size) {
    const float* h    = (const float*)d_in[0];
    const int*   mask = (const int*)  d_in[1];
    const float* lng  = (const float*)d_in[2];
    const float* lnb  = (const float*)d_in[3];
    const float* Wout = (const float*)d_in[4];
    const float* Wnm  = (const float*)d_in[5];
    const float* bnm  = (const float*)d_in[6];
    const float* Wwg  = (const float*)d_in[7];
    const float* bwg  = (const float*)d_in[8];
    float* out = (float*)d_out;

    cudaFuncSetAttribute(chunk_kernel,
                         cudaFuncAttributeMaxDynamicSharedMemorySize,
                         SMEM_BYTES);
    cudaFuncSetAttribute(recon_kernel,
                         cudaFuncAttributeMaxDynamicSharedMemorySize,
                         RSMEM_BYTES);

    init_kernel<<<448, 256>>>();
    pre_kernel<<<Bq * NCq + Bq * (NCq - 1), 256>>>(h, Wnm, Wwg);

    for (int c = 0; c < NCq; ++c)
        chunk_kernel<<<136, 256, SMEM_BYTES>>>(h, mask, bnm, Wwg, bwg, c);

    recon_kernel<<<Bq * NCq, 256, RSMEM_BYTES>>>();
    mbuild_kernel<<<NCq * 56, 256>>>(h);
    stats_kernel<<<GM / 8, 256>>>();

    dim3 grid(GN / 128, GM / 128);
    gemm_kernel<<<grid, 256>>>(Wout, h, lng, lnb, out);
}

// round 15
// speedup vs baseline: 1.8147x; 1.0679x over previous
#include <cuda_runtime.h>
#include <math.h>

#define Bq 8
#define Tq 4096
#define Dq 896
#define Sq 64
#define Cq 128
#define NCq 32

#define GM (Bq*Tq)
#define GN Dq
#define GK Dq

// ---------------- global scratch ----------------
__device__ float g_G[Bq][NCq][Cq][Cq];
__device__ float g_Gx[Bq][NCq][Cq][Cq];
__device__ float g_hd[Bq][Tq][4];
__device__ float g_Ball[NCq][Bq][Sq][Dq];
__device__ float g_P0[Bq][Cq][Sq];
__device__ float g_u[Bq][Sq];
__device__ float g_beta[Bq][NCq][Cq][Sq];
__device__ float g_gamma[Bq][NCq][Cq][Cq];
__device__ float g_afinC[NCq][Bq][Sq];
__device__ float g_kapC[NCq][Bq][Cq];
__device__ int   g_idxC[NCq][Bq][Cq];
__device__ unsigned g_mskC[NCq][Bq][Sq][4];
__device__ float g_E[Bq][NCq][Cq][Sq];
__device__ float g_invA[Bq][NCq][Cq];
__device__ float g_wgA[Bq][NCq][Cq];
__device__ int   g_miA[Bq][NCq][Cq];
__device__ float g_m[(size_t)Bq*Tq*Dq];
__device__ float g_stats[(size_t)Bq*Tq][2];

// chunk_kernel scan smem layout (float offsets)
#define OF_Q    0
#define OF_G    8320
#define OF_GX   24704
#define OF_HD   41088
#define OF_A    41600
#define OF_R    41664
#define OF_IDX  41792
#define OF_MSK  41920
#define OF_KF   42176
#define SMEM_FLOATS 42304
#define SMEM_BYTES (SMEM_FLOATS*4)

// recon smem layout
#define RS_E    0
#define RS_A    8192
#define RS_R    16384
#define RS_INV  16512
#define RS_WG   16640
#define RS_MI   16768
#define RSMEM_FLOATS 16896
#define RSMEM_BYTES (RSMEM_FLOATS*4)

__device__ __forceinline__ unsigned okey(float f) {
    unsigned u = __float_as_uint(f);
    return (u & 0x80000000u) ? ~u : (u | 0x80000000u);
}
__device__ __forceinline__ float dekey(unsigned k) {
    unsigned u = (k & 0x80000000u) ? (k ^ 0x80000000u) : ~k;
    return __uint_as_float(u);
}
__device__ __forceinline__ float to_tf32(float v) {
    unsigned r;
    asm("cvt.rna.tf32.f32 %0, %1;" : "=r"(r) : "f"(v));
    return __uint_as_float(r);
}

// ---------------------------------------------------------------------
__global__ void init_kernel() {
    int tid = blockIdx.x * blockDim.x + threadIdx.x;
    int stride = gridDim.x * blockDim.x;
    int nb = Bq * Sq * Dq;
    for (int i = tid; i < nb; i += stride) (&g_Ball[0][0][0][0])[i] = 0.f;
    int np = Bq * Cq * Sq;
    for (int i = tid; i < np; i += stride) (&g_P0[0][0][0])[i] = 0.f;
    if (tid < Bq * Sq) (&g_u[0][0])[tid] = 0.f;
}

// ---------------------------------------------------------------------
__global__ __launch_bounds__(256) void pre_kernel(
    const float* __restrict__ h,
    const float* __restrict__ W_nm,
    const float* __restrict__ W_wg)
{
    __shared__ float As[8][128];
    __shared__ float Bs[8][128];

    const int tid = threadIdx.x;
    const int tr = tid >> 4, tc = tid & 15;
    const int lr = tid >> 1, lk = (tid & 1) * 4;

    int b, c;
    const float *Arow, *Brow;
    float* outp;
    bool doHd;
    if (blockIdx.x < Bq * NCq) {
        b = blockIdx.x / NCq; c = blockIdx.x % NCq;
        Arow = h + ((size_t)b * Tq + c * Cq) * Dq;
        Brow = Arow;
        outp = &g_G[b][c][0][0];
        doHd = true;
    } else {
        int k = blockIdx.x - Bq * NCq;
        b = k / (NCq - 1); c = k % (NCq - 1);
        Arow = h + ((size_t)b * Tq + (c + 1) * Cq) * Dq;
        Brow = h + ((size_t)b * Tq + c * Cq) * Dq;
        outp = &g_Gx[b][c][0][0];
        doHd = false;
    }

    float acc[8][8];
    #pragma unroll
    for (int i = 0; i < 8; ++i)
        #pragma unroll
        for (int j = 0; j < 8; ++j) acc[i][j] = 0.f;

    float4 av = *(const float4*)(Arow + (size_t)lr * Dq + lk);
    float4 bv = *(const float4*)(Brow + (size_t)lr * Dq + lk);
    for (int k0 = 0; k0 < Dq; k0 += 8) {
        __syncthreads();
        As[lk + 0][lr] = av.x; As[lk + 1][lr] = av.y;
        As[lk + 2][lr] = av.z; As[lk + 3][lr] = av.w;
        Bs[lk + 0][lr] = bv.x; Bs[lk + 1][lr] = bv.y;
        Bs[lk + 2][lr] = bv.z; Bs[lk + 3][lr] = bv.w;
        __syncthreads();
        if (k0 + 8 < Dq) {
            av = *(const float4*)(Arow + (size_t)lr * Dq + k0 + 8 + lk);
            bv = *(const float4*)(Brow + (size_t)lr * Dq + k0 + 8 + lk);
        }
        #pragma unroll
        for (int kk = 0; kk < 8; ++kk) {
            float a[8], bb[8];
            #pragma unroll
            for (int i = 0; i < 8; ++i) a[i]  = As[kk][tr + 16 * i];
            #pragma unroll
            for (int j = 0; j < 8; ++j) bb[j] = Bs[kk][tc + 16 * j];
            #pragma unroll
            for (int i = 0; i < 8; ++i)
                #pragma unroll
                for (int j = 0; j < 8; ++j)
                    acc[i][j] = fmaf(a[i], bb[j], acc[i][j]);
        }
    }
    #pragma unroll
    for (int i = 0; i < 8; ++i)
        #pragma unroll
        for (int j = 0; j < 8; ++j)
            outp[(tr + 16 * i) * Cq + tc + 16 * j] = acc[i][j];

    if (doHd) {
        const int w = tid >> 5, l = tid & 31;
        const int t0 = c * Cq;
        for (int r = w; r < Cq; r += 8) {
            const float* hr = Arow + (size_t)r * Dq;
            float s0 = 0.f, s1 = 0.f, s2 = 0.f;
            for (int d = l; d < Dq; d += 32) {
                float x = hr[d];
                s0 += x * W_nm[d];
                s1 += x * W_nm[Dq + d];
                s2 += x * W_wg[d];
            }
            #pragma unroll
            for (int o = 16; o > 0; o >>= 1) {
                s0 += __shfl_xor_sync(0xffffffffu, s0, o);
                s1 += __shfl_xor_sync(0xffffffffu, s1, o);
                s2 += __shfl_xor_sync(0xffffffffu, s2, o);
            }
            if (l == 0) {
                g_hd[b][t0 + r][0] = s0;
                g_hd[b][t0 + r][1] = s1;
                g_hd[b][t0 + r][2] = s2;
                g_hd[b][t0 + r][3] = 0.f;
            }
        }
    }
}

// ---------------------------------------------------------------------
// chunk launch c: scan (blocks 0..7, G/Gx staged PRE-SCALED by 1/sqrt(D),
// pe/pd via int REDUX) + B-path (blocks 8..135)
// ---------------------------------------------------------------------
__global__ __launch_bounds__(256) void chunk_kernel(
    const float* __restrict__ h, const int* __restrict__ mask,
    const float* __restrict__ b_nm, const float* __restrict__ W_wg,
    const float* __restrict__ b_wg, int c)
{
    extern __shared__ float sm[];
    const int tid = threadIdx.x;
    const float scale = rsqrtf((float)Dq);

    if (blockIdx.x < 8) {
        float*    Qs   = sm + OF_Q;
        float*    sG   = sm + OF_G;
        float*    sGx  = sm + OF_GX;
        float4*   sHd  = (float4*)(sm + OF_HD);
        float*    Asm  = sm + OF_A;
        float*    rS   = sm + OF_R;
        int*      idxS = (int*)(sm + OF_IDX);
        unsigned* mskS = (unsigned*)(sm + OF_MSK);
        float*    kapF = sm + OF_KF;

        const int b = blockIdx.x;
        const int t0 = c * Cq;

        if (tid < Cq) {
            float4 hv = ((const float4*)g_hd)[(size_t)b * Tq + t0 + tid];
            hv.w = (float)mask[b * Tq + t0 + tid];
            sHd[tid] = hv;
        }
        {
            const float4* gsrc = (const float4*)&g_G[b][c][0][0];
            #pragma unroll 4
            for (int i = tid; i < Cq * Cq / 4; i += 256) {
                float4 v = gsrc[i];
                v.x *= scale; v.y *= scale; v.z *= scale; v.w *= scale;
                ((float4*)sG)[i] = v;
            }
        }
        if (c > 0) {
            const float4* xsrc = (const float4*)&g_Gx[b][c - 1][0][0];
            #pragma unroll 4
            for (int i = tid; i < Cq * Cq / 4; i += 256) {
                float4 v = xsrc[i];
                v.x *= scale; v.y *= scale; v.z *= scale; v.w *= scale;
                ((float4*)sGx)[i] = v;
            }
            if (tid < Sq) Asm[tid] = g_afinC[c - 1][b][tid] * scale;
            if (tid < Cq) {
                kapF[tid] = g_kapC[c - 1][b][tid];
                idxS[tid] = g_idxC[c - 1][b][tid];
            }
        }
        __syncthreads();

        if (c == 0) {
            for (int i = tid; i < Cq * Sq; i += 256) {
                int tau = i >> 6, s = i & 63;
                Qs[tau * 65 + s] = 0.f;
            }
        } else {
            const int t = tid >> 1, hf = (tid & 1) * 32;
            const float* P0r = &g_P0[b][t][0];
            float* Qr = Qs + t * 65;
            #pragma unroll 8
            for (int q = 0; q < 32; ++q) {
                int s = hf + q;
                Qr[s] = Asm[s] * P0r[s];
            }
            const float* gxr = sGx + t * Cq;
            for (int j = 0; j < Cq; ++j) {
                int s = idxS[j];
                if ((unsigned)(s - hf) < 32u)
                    Qr[s] = fmaf(kapF[j], gxr[j], Qr[s]);
            }
        }
        __syncthreads();
        if (tid < Sq) Asm[tid] = 1.f;
        if (tid < Cq) { rS[tid] = 0.f; idxS[tid] = 0; }
        mskS[tid] = 0;
        __syncthreads();

        if (tid < 32) {
            const int l = tid;
            const float wwgg = W_wg[Dq];
            const float bnm = b_nm[0], bwg = b_wg[0];
            float A0 = 1.f, A1 = 1.f;
            float R0 = g_u[b][l], R1 = g_u[b][l + 32];
            float* gE = &g_E[b][c][0][0];
            float* gInv = &g_invA[b][c][0];
            float* gWg  = &g_wgA[b][c][0];
            int*   gMi  = &g_miA[b][c][0];

            for (int t = 0; t < Cq; ++t) {
                const float* gr = sG + t * Cq;
                float g0 = gr[l], g1 = gr[l + 32];
                float g2 = gr[l + 64], g3 = gr[l + 96];

                float s0 = Qs[t * 65 + l];
                float s1 = Qs[t * 65 + l + 32];

                unsigned k0 = okey(s0), k1 = okey(s1);
                unsigned kmx = __reduce_max_sync(0xffffffffu, k0 > k1 ? k0 : k1);
                float mx = dekey(kmx);
                unsigned b0 = __ballot_sync(0xffffffffu, k0 == kmx);
                unsigned b1 = __ballot_sync(0xffffffffu, k1 == kmx);
                int mi = b0 ? (__ffs(b0) - 1) : (__ffs(b1) + 31);

                float e0 = __expf(s0 - mx), e1 = __expf(s1 - mx);
                gE[t * Sq + l] = e0;
                gE[t * Sq + l + 32] = e1;

                // fixed-point HW warp reductions (sm_103: int redux only)
                int pei = __float2int_rn((e0 + e1) * 16777216.f);       // 2^24
                int pdi = __float2int_rn(fmaf(e0, R0, e1 * R1) * 524288.f); // 2^19
                pei = __reduce_add_sync(0xffffffffu, pei);
                pdi = __reduce_add_sync(0xffffffffu, pdi);
                float pe = (float)pei * 5.9604645e-8f;
                float pd = (float)pdi * 1.9073486e-6f;

                float inv = __fdividef(1.f, pe);
                float mdot = pd * inv;

                float4 hdt = sHd[t];
                float gg = __fdividef(1.f, 1.f + __expf(-(hdt.x + mdot + bnm)));
                float wg = __fdividef(1.f, 1.f + __expf(-(hdt.z + gg * wwgg + bwg)));
                wg = fminf(wg, 0.2f) * hdt.w;

                if (l == 0) gInv[t] = inv;
                if (l == 1) gWg[t] = wg;
                if (l == 2) gMi[t] = mi;

                float dec = 1.f - wg;
                if (mi == l) {
                    A0 *= dec;
                    R0 = fmaf(dec, R0, wg * hdt.y);
                    Asm[mi] = A0;
                    rS[t] = wg / A0;
                    idxS[t] = mi;
                    mskS[mi * 4 + (t >> 5)] |= 1u << (t & 31);
                } else if (mi == l + 32) {
                    A1 *= dec;
                    R1 = fmaf(dec, R1, wg * hdt.y);
                    Asm[mi] = A1;
                    rS[t] = wg / A1;
                    idxS[t] = mi;
                    mskS[mi * 4 + (t >> 5)] |= 1u << (t & 31);
                }
                {
                    float v;
                    v = Qs[l * 65 + mi];
                    Qs[l * 65 + mi] = fmaf(dec, v, wg * g0);
                    v = Qs[(l + 32) * 65 + mi];
                    Qs[(l + 32) * 65 + mi] = fmaf(dec, v, wg * g1);
                    v = Qs[(l + 64) * 65 + mi];
                    Qs[(l + 64) * 65 + mi] = fmaf(dec, v, wg * g2);
                    v = Qs[(l + 96) * 65 + mi];
                    Qs[(l + 96) * 65 + mi] = fmaf(dec, v, wg * g3);
                }
                __syncwarp();
            }

            g_u[b][l] = R0; g_u[b][l + 32] = R1;
            g_afinC[c][b][l] = A0; g_afinC[c][b][l + 32] = A1;
            #pragma unroll
            for (int q = 0; q < 4; ++q) {
                int j = l + 32 * q;
                int ix = idxS[j];
                g_kapC[c][b][j] = rS[j] * Asm[ix];
                g_idxC[c][b][j] = ix;
            }
        }
        __syncthreads();
        ((unsigned*)&g_mskC[c][b][0][0])[tid] = mskS[tid];
    } else {
        if (c == 0) return;
        const int id = blockIdx.x - 8;
        const int b = id >> 4, s0 = (id & 15) * 4;

        float*    kap2 = sm;
        float*    af4  = sm + 128;
        unsigned* msk4 = (unsigned*)(sm + 132);
        float*    Bsm  = sm + 160;

        if (tid < Cq) kap2[tid] = g_kapC[c - 1][b][tid];
        if (tid < 4)  af4[tid] = g_afinC[c - 1][b][s0 + tid];
        if (tid < 16) msk4[tid] = ((unsigned*)&g_mskC[c - 1][b][s0][0])[tid];
        __syncthreads();

        const float* Hp = h + ((size_t)b * Tq + (c - 1) * Cq) * Dq;
        if (tid < 224) {
            #pragma unroll
            for (int k = 0; k < 4; ++k) {
                const int s = s0 + k;
                float4 v = ((const float4*)&g_Ball[c - 1][b][s][0])[tid];
                const float as = af4[k];
                v.x *= as; v.y *= as; v.z *= as; v.w *= as;
                #pragma unroll
                for (int w2 = 0; w2 < 4; ++w2) {
                    unsigned wd = msk4[k * 4 + w2];
                    while (wd) {
                        int bp = __ffs(wd) - 1; wd &= wd - 1;
                        int j = w2 * 32 + bp;
                        float kj = kap2[j];
                        float4 hv = ((const float4*)(Hp + (size_t)j * Dq))[tid];
                        v.x = fmaf(kj, hv.x, v.x); v.y = fmaf(kj, hv.y, v.y);
                        v.z = fmaf(kj, hv.z, v.z); v.w = fmaf(kj, hv.w, v.w);
                    }
                }
                ((float4*)&g_Ball[c][b][s][0])[tid] = v;
                ((float4*)&Bsm[k * Dq])[tid] = v;
            }
        }
        __syncthreads();

        if (c < NCq - 1) {
            const int t = tid >> 1, sp = (tid & 1) * 2;
            const float4* Hn = (const float4*)(h + ((size_t)b * Tq + (c + 1) * Cq + t) * Dq);
            const float4* Ba = (const float4*)&Bsm[(sp + 0) * Dq];
            const float4* Bb = (const float4*)&Bsm[(sp + 1) * Dq];
            float a0 = 0.f, a1 = 0.f;
            #pragma unroll 4
            for (int k = 0; k < Dq / 4; ++k) {
                float4 hv = Hn[k];
                float4 x = Ba[k];
                a0 += hv.x * x.x + hv.y * x.y + hv.z * x.z + hv.w * x.w;
                float4 y = Bb[k];
                a1 += hv.x * y.x + hv.y * y.y + hv.z * y.z + hv.w * y.w;
            }
            g_P0[b][t][s0 + sp + 0] = a0;
            g_P0[b][t][s0 + sp + 1] = a1;
        }
    }
}

// ---------------------------------------------------------------------
__global__ __launch_bounds__(256) void recon_kernel() {
    extern __shared__ float rs[];
    float* sE   = rs + RS_E;
    float* sA   = rs + RS_A;
    float* sr   = rs + RS_R;
    float* sinv = rs + RS_INV;
    float* swg  = rs + RS_WG;
    int*   smi  = (int*)(rs + RS_MI);

    const int b = blockIdx.x >> 5;
    const int c = blockIdx.x & 31;
    const int tid = threadIdx.x;

    const float4* esrc = (const float4*)&g_E[b][c][0][0];
    #pragma unroll 4
    for (int i = tid; i < Cq * Sq / 4; i += 256) ((float4*)sE)[i] = esrc[i];
    if (tid < Cq) {
        sinv[tid] = g_invA[b][c][tid];
        swg[tid]  = g_wgA[b][c][tid];
        smi[tid]  = g_miA[b][c][tid];
    }
    __syncthreads();

    if (tid < Sq) {
        float A = 1.f;
        for (int t = 0; t < Cq; ++t) {
            sA[t * Sq + tid] = A;
            if (smi[t] == tid) {
                A *= (1.f - swg[t]);
                sr[t] = swg[t] / A;
            }
        }
    }
    __syncthreads();

    float* bet = &g_beta[b][c][0][0];
    for (int i = tid; i < Cq * Sq; i += 256) {
        int t = i >> 6;
        bet[i] = sE[i] * sinv[t] * sA[i];
    }
    float* gam = &g_gamma[b][c][0][0];
    for (int i = tid; i < Cq * Cq; i += 256) {
        int t = i >> 7, j = i & 127;
        float gv = 0.f;
        if (j < t) {
            int ix = smi[j];
            gv = sE[t * Sq + ix] * sinv[t] * sr[j] * sA[t * Sq + ix];
        }
        gam[i] = gv;
    }
}

// ---------------------------------------------------------------------
// mbuild: m = [beta|gamma] @ [B_c ; H_c] via tf32 mma (M=128,N=128,K=192)
// ---------------------------------------------------------------------
__global__ __launch_bounds__(256) void mbuild_kernel(const float* __restrict__ h)
{
    __shared__ float As[16][132];
    __shared__ float Bs[16][132];

    const int cc = blockIdx.x / 56;
    const int r  = blockIdx.x % 56;
    const int b  = r / 7;
    const int n0 = (r % 7) * 128;
    const int t0 = cc * Cq;
    const int tid = threadIdx.x;
    const int lane = tid & 31;
    const int warp = tid >> 5;
    const int wm = (warp >> 1) * 32;
    const int wn = (warp & 1) * 64;
    const int gr = lane >> 2;
    const int gc = lane & 3;

    const float* Bold = &g_Ball[cc][b][0][0];
    const float* Hc = h + ((size_t)b * Tq + t0) * Dq;
    const float* bet = &g_beta[b][cc][0][0];
    const float* gam = &g_gamma[b][cc][0][0];

    const int lr0 = tid >> 2;          // 0..63 (A rows, +64 for second)
    const int kc  = (tid & 3) * 4;     // 0,4,8,12
    const int kr  = tid >> 4;          // 0..15 (B k-row)
    const int nc8 = (tid & 15) * 8;    // 0..120

    float acc[2][8][4];
    #pragma unroll
    for (int mt = 0; mt < 2; ++mt)
        #pragma unroll
        for (int nt = 0; nt < 8; ++nt)
            #pragma unroll
            for (int q = 0; q < 4; ++q) acc[mt][nt][q] = 0.f;

    for (int k0 = 0; k0 < Sq + Cq; k0 += 16) {
        float4 a0, a1;
        if (k0 < Sq) {
            a0 = *(const float4*)(bet + lr0 * Sq + k0 + kc);
            a1 = *(const float4*)(bet + (lr0 + 64) * Sq + k0 + kc);
        } else {
            a0 = *(const float4*)(gam + lr0 * Cq + k0 - Sq + kc);
            a1 = *(const float4*)(gam + (lr0 + 64) * Cq + k0 - Sq + kc);
        }
        int kg = k0 + kr;
        const float* rp = (kg < Sq) ? (Bold + (size_t)kg * Dq)
                                    : (Hc + (size_t)(kg - Sq) * Dq);
        float4 b0 = *(const float4*)(rp + n0 + nc8);
        float4 b1 = *(const float4*)(rp + n0 + nc8 + 4);
        __syncthreads();
        As[kc + 0][lr0] = to_tf32(a0.x); As[kc + 1][lr0] = to_tf32(a0.y);
        As[kc + 2][lr0] = to_tf32(a0.z); As[kc + 3][lr0] = to_tf32(a0.w);
        As[kc + 0][lr0 + 64] = to_tf32(a1.x); As[kc + 1][lr0 + 64] = to_tf32(a1.y);
        As[kc + 2][lr0 + 64] = to_tf32(a1.z); As[kc + 3][lr0 + 64] = to_tf32(a1.w);
        Bs[kr][nc8 + 0] = to_tf32(b0.x); Bs[kr][nc8 + 1] = to_tf32(b0.y);
        Bs[kr][nc8 + 2] = to_tf32(b0.z); Bs[kr][nc8 + 3] = to_tf32(b0.w);
        Bs[kr][nc8 + 4] = to_tf32(b1.x); Bs[kr][nc8 + 5] = to_tf32(b1.y);
        Bs[kr][nc8 + 6] = to_tf32(b1.z); Bs[kr][nc8 + 7] = to_tf32(b1.w);
        __syncthreads();
        #pragma unroll
        for (int ks = 0; ks < 16; ks += 8) {
            unsigned afr[2][4];
            #pragma unroll
            for (int mt = 0; mt < 2; ++mt) {
                int row = wm + mt * 16 + gr;
                afr[mt][0] = __float_as_uint(As[ks + gc][row]);
                afr[mt][1] = __float_as_uint(As[ks + gc][row + 8]);
                afr[mt][2] = __float_as_uint(As[ks + gc + 4][row]);
                afr[mt][3] = __float_as_uint(As[ks + gc + 4][row + 8]);
            }
            unsigned bfr[8][2];
            #pragma unroll
            for (int nt = 0; nt < 8; ++nt) {
                int col = wn + nt * 8 + gr;
                bfr[nt][0] = __float_as_uint(Bs[ks + gc][col]);
                bfr[nt][1] = __float_as_uint(Bs[ks + gc + 4][col]);
            }
            #pragma unroll
            for (int mt = 0; mt < 2; ++mt)
                #pragma unroll
                for (int nt = 0; nt < 8; ++nt) {
                    asm volatile(
                        "mma.sync.aligned.m16n8k8.row.col.f32.tf32.tf32.f32 "
                        "{%0,%1,%2,%3}, {%4,%5,%6,%7}, {%8,%9}, {%0,%1,%2,%3};"
                        : "+f"(acc[mt][nt][0]), "+f"(acc[mt][nt][1]),
                          "+f"(acc[mt][nt][2]), "+f"(acc[mt][nt][3])
                        : "r"(afr[mt][0]), "r"(afr[mt][1]),
                          "r"(afr[mt][2]), "r"(afr[mt][3]),
                          "r"(bfr[nt][0]), "r"(bfr[nt][1]));
                }
        }
    }

    #pragma unroll
    for (int mt = 0; mt < 2; ++mt) {
        #pragma unroll
        for (int nt = 0; nt < 8; ++nt) {
            size_t r0 = (size_t)b * Tq + t0 + wm + mt * 16 + gr;
            size_t r1 = r0 + 8;
            int n = n0 + wn + nt * 8 + 2 * gc;
            g_m[r0 * Dq + n]     = acc[mt][nt][0];
            g_m[r0 * Dq + n + 1] = acc[mt][nt][1];
            g_m[r1 * Dq + n]     = acc[mt][nt][2];
            g_m[r1 * Dq + n + 1] = acc[mt][nt][3];
        }
    }
}

// ---------------------------------------------------------------------
__global__ __launch_bounds__(256) void stats_kernel() {
    int row = blockIdx.x * 8 + (threadIdx.x >> 5);
    int l = threadIdx.x & 31;
    const float* mr = g_m + (size_t)row * Dq;
    float s = 0.f, s2 = 0.f;
    for (int d = l; d < Dq; d += 32) { float v = mr[d]; s += v; s2 += v * v; }
    #pragma unroll
    for (int o = 16; o > 0; o >>= 1) {
        s  += __shfl_xor_sync(0xffffffffu, s, o);
        s2 += __shfl_xor_sync(0xffffffffu, s2, o);
    }
    if (l == 0) {
        float mu = s * (1.f / (float)Dq);
        float var = s2 * (1.f / (float)Dq) - mu * mu;
        g_stats[row][0] = mu;
        g_stats[row][1] = rsqrtf(var + 1e-5f);
    }
}

// ---------------------------------------------------------------------
// final GEMM: tf32 mma.sync, 128x128x16 tiles, LN fused (unchanged R13)
// ---------------------------------------------------------------------
__global__ __launch_bounds__(256) void gemm_kernel(
    const float* __restrict__ Wt,
    const float* __restrict__ H,
    const float* __restrict__ lng,
    const float* __restrict__ lnb,
    float* __restrict__ C)
{
    __shared__ float As[16][132];
    __shared__ float Bs[16][132];

    const int bm = blockIdx.y * 128;
    const int bn = blockIdx.x * 128;
    const int tid = threadIdx.x;
    const int lane = tid & 31;
    const int warp = tid >> 5;
    const int wm = (warp >> 1) * 32;
    const int wn = (warp & 1) * 64;
    const int gr = lane >> 2;
    const int gc = lane & 3;

    const int lr0 = tid >> 2;
    const int kc  = (tid & 3) * 4;

    const float* Ap0 = g_m + (size_t)(bm + lr0) * GK + kc;
    const float* Ap1 = g_m + (size_t)(bm + lr0 + 64) * GK + kc;
    const float* Bp0 = Wt + (size_t)(bn + lr0) * GK + kc;
    const float* Bp1 = Wt + (size_t)(bn + lr0 + 64) * GK + kc;
    const float mu0 = g_stats[bm + lr0][0],      rs0 = g_stats[bm + lr0][1];
    const float mu1 = g_stats[bm + lr0 + 64][0], rs1 = g_stats[bm + lr0 + 64][1];

    float acc[2][8][4];
    #pragma unroll
    for (int mt = 0; mt < 2; ++mt)
        #pragma unroll
        for (int nt = 0; nt < 8; ++nt)
            #pragma unroll
            for (int q = 0; q < 4; ++q) acc[mt][nt][q] = 0.f;

    float4 pa0 = *(const float4*)(Ap0);
    float4 pa1 = *(const float4*)(Ap1);
    float4 pb0 = *(const float4*)(Bp0);
    float4 pb1 = *(const float4*)(Bp1);

    for (int k0 = 0; k0 < GK; k0 += 16) {
        float4 gv = *(const float4*)(lng + k0 + kc);
        float4 ov = *(const float4*)(lnb + k0 + kc);
        float4 a0 = pa0, a1 = pa1, b0 = pb0, b1 = pb1;
        a0.x = (a0.x - mu0) * rs0 * gv.x + ov.x;
        a0.y = (a0.y - mu0) * rs0 * gv.y + ov.y;
        a0.z = (a0.z - mu0) * rs0 * gv.z + ov.z;
        a0.w = (a0.w - mu0) * rs0 * gv.w + ov.w;
        a1.x = (a1.x - mu1) * rs1 * gv.x + ov.x;
        a1.y = (a1.y - mu1) * rs1 * gv.y + ov.y;
        a1.z = (a1.z - mu1) * rs1 * gv.z + ov.z;
        a1.w = (a1.w - mu1) * rs1 * gv.w + ov.w;
        __syncthreads();
        As[kc + 0][lr0] = to_tf32(a0.x); As[kc + 1][lr0] = to_tf32(a0.y);
        As[kc + 2][lr0] = to_tf32(a0.z); As[kc + 3][lr0] = to_tf32(a0.w);
        As[kc + 0][lr0 + 64] = to_tf32(a1.x); As[kc + 1][lr0 + 64] = to_tf32(a1.y);
        As[kc + 2][lr0 + 64] = to_tf32(a1.z); As[kc + 3][lr0 + 64] = to_tf32(a1.w);
        Bs[kc + 0][lr0] = to_tf32(b0.x); Bs[kc + 1][lr0] = to_tf32(b0.y);
        Bs[kc + 2][lr0] = to_tf32(b0.z); Bs[kc + 3][lr0] = to_tf32(b0.w);
        Bs[kc + 0][lr0 + 64] = to_tf32(b1.x); Bs[kc + 1][lr0 + 64] = to_tf32(b1.y);
        Bs[kc + 2][lr0 + 64] = to_tf32(b1.z); Bs[kc + 3][lr0 + 64] = to_tf32(b1.w);
        __syncthreads();
        if (k0 + 16 < GK) {
            pa0 = *(const float4*)(Ap0 + k0 + 16);
            pa1 = *(const float4*)(Ap1 + k0 + 16);
            pb0 = *(const float4*)(Bp0 + k0 + 16);
            pb1 = *(const float4*)(Bp1 + k0 + 16);
        }
        #pragma unroll
        for (int ks = 0; ks < 16; ks += 8) {
            unsigned afr[2][4];
            #pragma unroll
            for (int mt = 0; mt < 2; ++mt) {
                int row = wm + mt * 16 + gr;
                afr[mt][0] = __float_as_uint(As[ks + gc][row]);
                afr[mt][1] = __float_as_uint(As[ks + gc][row + 8]);
                afr[mt][2] = __float_as_uint(As[ks + gc + 4][row]);
                afr[mt][3] = __float_as_uint(As[ks + gc + 4][row + 8]);
            }
            unsigned bfr[8][2];
            #pragma unroll
            for (int nt = 0; nt < 8; ++nt) {
                int col = wn + nt * 8 + gr;
                bfr[nt][0] = __float_as_uint(Bs[ks + gc][col]);
                bfr[nt][1] = __float_as_uint(Bs[ks + gc + 4][col]);
            }
            #pragma unroll
            for (int mt = 0; mt < 2; ++mt)
                #pragma unroll
                for (int nt = 0; nt < 8; ++nt) {
                    asm volatile(
                        "mma.sync.aligned.m16n8k8.row.col.f32.tf32.tf32.f32 "
                        "{%0,%1,%2,%3}, {%4,%5,%6,%7}, {%8,%9}, {%0,%1,%2,%3};"
                        : "+f"(acc[mt][nt][0]), "+f"(acc[mt][nt][1]),
                          "+f"(acc[mt][nt][2]), "+f"(acc[mt][nt][3])
                        : "r"(afr[mt][0]), "r"(afr[mt][1]),
                          "r"(afr[mt][2]), "r"(afr[mt][3]),
                          "r"(bfr[nt][0]), "r"(bfr[nt][1]));
                }
        }
    }

    #pragma unroll
    for (int mt = 0; mt < 2; ++mt) {
        #pragma unroll
        for (int nt = 0; nt < 8; ++nt) {
            size_t r0 = (size_t)bm + wm + mt * 16 + gr;
            size_t r1 = r0 + 8;
            int n = bn + wn + nt * 8 + 2 * gc;
            float d0 = fminf(fmaxf(acc[mt][nt][0] * 0.5f, -2.f), 2.f);
            float d1 = fminf(fmaxf(acc[mt][nt][1] * 0.5f, -2.f), 2.f);
            float d2 = fminf(fmaxf(acc[mt][nt][2] * 0.5f, -2.f), 2.f);
            float d3 = fminf(fmaxf(acc[mt][nt][3] * 0.5f, -2.f), 2.f);
            C[r0 * GN + n]     = H[r0 * GN + n]     + d0;
            C[r0 * GN + n + 1] = H[r0 * GN + n + 1] + d1;
            C[r1 * GN + n]     = H[r1 * GN + n]     + d2;
            C[r1 * GN + n + 1] = H[r1 * GN + n + 1] + d3;
        }
    }
}

// ---------------------------------------------------------------------
extern "C" void kernel_launch(void* const* d_in, const int* in_sizes, int n_in,
                              void* d_out, int out_size) {
    const float* h    = (const float*)d_in[0];
    const int*   mask = (const int*)  d_in[1];
    const float* lng  = (const float*)d_in[2];
    const float* lnb  = (const float*)d_in[3];
    const float* Wout = (const float*)d_in[4];
    const float* Wnm  = (const float*)d_in[5];
    const float* bnm  = (const float*)d_in[6];
    const float* Wwg  = (const float*)d_in[7];
    const float* bwg  = (const float*)d_in[8];
    float* out = (float*)d_out;

    cudaFuncSetAttribute(chunk_kernel,
                         cudaFuncAttributeMaxDynamicSharedMemorySize,
                         SMEM_BYTES);
    cudaFuncSetAttribute(recon_kernel,
                         cudaFuncAttributeMaxDynamicSharedMemorySize,
                         RSMEM_BYTES);

    init_kernel<<<448, 256>>>();
    pre_kernel<<<Bq * NCq + Bq * (NCq - 1), 256>>>(h, Wnm, Wwg);

    for (int c = 0; c < NCq; ++c)
        chunk_kernel<<<136, 256, SMEM_BYTES>>>(h, mask, bnm, Wwg, bwg, c);

    recon_kernel<<<Bq * NCq, 256, RSMEM_BYTES>>>();
    mbuild_kernel<<<NCq * 56, 256>>>(h);
    stats_kernel<<<GM / 8, 256>>>();

    dim3 grid(GN / 128, GM / 128);
    gemm_kernel<<<grid, 256>>>(Wout, h, lng, lnb, out);
}

// round 17
// speedup vs baseline: 1.9227x; 1.0595x over previous
#include <cuda_runtime.h>
#include <math.h>

#define Bq 8
#define Tq 4096
#define Dq 896
#define Sq 64
#define Cq 128
#define NCq 32

#define GM (Bq*Tq)
#define GN Dq
#define GK Dq

// ---------------- global scratch ----------------
__device__ float g_G[Bq][NCq][Cq][Cq];
__device__ float g_Gx[Bq][NCq][Cq][Cq];
__device__ float g_hd[Bq][Tq][4];
__device__ float g_Ball[NCq][Bq][Sq][Dq];
__device__ float g_P0[Bq][Cq][Sq];
__device__ float g_u[Bq][Sq];
__device__ float g_beta[Bq][NCq][Cq][Sq];
__device__ float g_gamma[Bq][NCq][Cq][Cq];
__device__ float g_afinC[NCq][Bq][Sq];
__device__ float g_kapC[NCq][Bq][Cq];
__device__ int   g_idxC[NCq][Bq][Cq];
__device__ unsigned g_mskC[NCq][Bq][Sq][4];
__device__ float g_E[Bq][NCq][Cq][Sq];
__device__ float g_invA[Bq][NCq][Cq];
__device__ float g_wgA[Bq][NCq][Cq];
__device__ int   g_miA[Bq][NCq][Cq];
__device__ float g_m[(size_t)Bq*Tq*Dq];
__device__ float g_stats[(size_t)Bq*Tq][2];

// chunk_kernel scan smem layout (float offsets)
#define OF_Q    0
#define OF_G    8320
#define OF_GX   24704
#define OF_HD   41088
#define OF_A    41600
#define OF_R    41664
#define OF_IDX  41792
#define OF_MSK  41920
#define OF_KF   42176
#define SMEM_FLOATS 42304
#define SMEM_BYTES (SMEM_FLOATS*4)

// recon smem layout
#define RS_E    0
#define RS_A    8192
#define RS_R    16384
#define RS_INV  16512
#define RS_WG   16640
#define RS_MI   16768
#define RSMEM_FLOATS 16896
#define RSMEM_BYTES (RSMEM_FLOATS*4)

__device__ __forceinline__ unsigned okey(float f) {
    unsigned u = __float_as_uint(f);
    return (u & 0x80000000u) ? ~u : (u | 0x80000000u);
}
__device__ __forceinline__ float dekey(unsigned k) {
    unsigned u = (k & 0x80000000u) ? (k ^ 0x80000000u) : ~k;
    return __uint_as_float(u);
}
__device__ __forceinline__ float to_tf32(float v) {
    unsigned r;
    asm("cvt.rna.tf32.f32 %0, %1;" : "=r"(r) : "f"(v));
    return __uint_as_float(r);
}

#define MMA_TF32(acc, a0, a1, a2, a3, b0, b1)                              \
    asm volatile(                                                           \
        "mma.sync.aligned.m16n8k8.row.col.f32.tf32.tf32.f32 "              \
        "{%0,%1,%2,%3}, {%4,%5,%6,%7}, {%8,%9}, {%0,%1,%2,%3};"            \
        : "+f"((acc)[0]), "+f"((acc)[1]), "+f"((acc)[2]), "+f"((acc)[3])   \
        : "r"(a0), "r"(a1), "r"(a2), "r"(a3), "r"(b0), "r"(b1))

// ---------------------------------------------------------------------
// gram tile: rows [tile*32, tile*32+32) x cols [0,128) of Arow . Brow^T
// fp32 SIMT (argmax-critical; accumulation order = sequential k).
// Called by all 256 threads of a block. ~33us of fp32 FMA.
// ---------------------------------------------------------------------
__device__ void gram_tile32(const float* __restrict__ Arow,
                            const float* __restrict__ Brow,
                            float* __restrict__ outp, int tile)
{
    __shared__ float As[8][36];
    __shared__ float Bs[8][132];

    const int tid = threadIdx.x;
    const int tr = tid >> 5, tc = tid & 31;     // compute: 8x32 thread grid
    const int lr = tid >> 1, lk = (tid & 1) * 4; // B loader: 128 rows
    const int ar = (tid < 64) ? (tid >> 1) : 0;  // A loader rows 0..31

    const float* Bp = Brow + (size_t)lr * Dq + lk;
    const float* Ap = Arow + (size_t)(tile * 32 + ar) * Dq + lk;

    float acc[4][4];
    #pragma unroll
    for (int i = 0; i < 4; ++i)
        #pragma unroll
        for (int j = 0; j < 4; ++j) acc[i][j] = 0.f;

    float4 av = make_float4(0.f, 0.f, 0.f, 0.f);
    if (tid < 64) av = *(const float4*)Ap;
    float4 bv = *(const float4*)Bp;

    for (int k0 = 0; k0 < Dq; k0 += 8) {
        __syncthreads();
        if (tid < 64) {
            As[lk + 0][ar] = av.x; As[lk + 1][ar] = av.y;
            As[lk + 2][ar] = av.z; As[lk + 3][ar] = av.w;
        }
        Bs[lk + 0][lr] = bv.x; Bs[lk + 1][lr] = bv.y;
        Bs[lk + 2][lr] = bv.z; Bs[lk + 3][lr] = bv.w;
        __syncthreads();
        if (k0 + 8 < Dq) {
            if (tid < 64) av = *(const float4*)(Ap + k0 + 8);
            bv = *(const float4*)(Bp + k0 + 8);
        }
        #pragma unroll
        for (int kk = 0; kk < 8; ++kk) {
            float a[4], b[4];
            #pragma unroll
            for (int i = 0; i < 4; ++i) a[i] = As[kk][tr + 8 * i];
            #pragma unroll
            for (int j = 0; j < 4; ++j) b[j] = Bs[kk][tc + 32 * j];
            #pragma unroll
            for (int i = 0; i < 4; ++i)
                #pragma unroll
                for (int j = 0; j < 4; ++j)
                    acc[i][j] = fmaf(a[i], b[j], acc[i][j]);
        }
    }
    #pragma unroll
    for (int i = 0; i < 4; ++i)
        #pragma unroll
        for (int j = 0; j < 4; ++j)
            outp[(tile * 32 + tr + 8 * i) * Cq + tc + 32 * j] = acc[i][j];
}

// ---------------------------------------------------------------------
// hd rows: 3 dot products per row for one (b, chunk)
// ---------------------------------------------------------------------
__device__ void hd_rows(const float* __restrict__ Arow,
                        const float* __restrict__ W_nm,
                        const float* __restrict__ W_wg,
                        int b, int t0)
{
    const int tid = threadIdx.x;
    const int w = tid >> 5, l = tid & 31;
    for (int r = w; r < Cq; r += 8) {
        const float* hr = Arow + (size_t)r * Dq;
        float s0 = 0.f, s1 = 0.f, s2 = 0.f;
        for (int d = l; d < Dq; d += 32) {
            float x = hr[d];
            s0 += x * W_nm[d];
            s1 += x * W_nm[Dq + d];
            s2 += x * W_wg[d];
        }
        #pragma unroll
        for (int o = 16; o > 0; o >>= 1) {
            s0 += __shfl_xor_sync(0xffffffffu, s0, o);
            s1 += __shfl_xor_sync(0xffffffffu, s1, o);
            s2 += __shfl_xor_sync(0xffffffffu, s2, o);
        }
        if (l == 0) {
            g_hd[b][t0 + r][0] = s0;
            g_hd[b][t0 + r][1] = s1;
            g_hd[b][t0 + r][2] = s2;
            g_hd[b][t0 + r][3] = 0.f;
        }
    }
}

// ---------------------------------------------------------------------
__global__ void init_kernel() {
    int tid = blockIdx.x * blockDim.x + threadIdx.x;
    int stride = gridDim.x * blockDim.x;
    int nb = Bq * Sq * Dq;
    for (int i = tid; i < nb; i += stride) (&g_Ball[0][0][0][0])[i] = 0.f;
    int np = Bq * Cq * Sq;
    for (int i = tid; i < np; i += stride) (&g_P0[0][0][0])[i] = 0.f;
    if (tid < Bq * Sq) (&g_u[0][0])[tid] = 0.f;
}

// ---------------------------------------------------------------------
// pre0: G[b][0] tiles + hd(chunk 0). grid = 40.
// ---------------------------------------------------------------------
__global__ __launch_bounds__(256) void pre0_kernel(
    const float* __restrict__ h,
    const float* __restrict__ W_nm,
    const float* __restrict__ W_wg)
{
    if (blockIdx.x < 32) {
        int b = blockIdx.x >> 2, tile = blockIdx.x & 3;
        const float* Ar = h + (size_t)b * Tq * Dq;
        gram_tile32(Ar, Ar, &g_G[b][0][0][0], tile);
    } else {
        int b = blockIdx.x - 32;
        hd_rows(h + (size_t)b * Tq * Dq, W_nm, W_wg, b, 0);
    }
}

// ---------------------------------------------------------------------
// chunk launch c (grid 208):
//  0..7     scan(c)
//  8..135   B-path(c)
//  136..167 G[b][c+1] tiles (hidden pre for next launch)
//  168..199 Gx[b][c] tiles
//  200..207 hd(c+1)
// ---------------------------------------------------------------------
__global__ __launch_bounds__(256) void chunk_kernel(
    const float* __restrict__ h, const int* __restrict__ mask,
    const float* __restrict__ b_nm, const float* __restrict__ W_nm,
    const float* __restrict__ W_wg, const float* __restrict__ b_wg, int c)
{
    extern __shared__ float sm[];
    const int tid = threadIdx.x;
    const float scale = rsqrtf((float)Dq);

    if (blockIdx.x < 8) {
        float*    Qs   = sm + OF_Q;
        float*    sG   = sm + OF_G;
        float*    sGx  = sm + OF_GX;
        float4*   sHd  = (float4*)(sm + OF_HD);
        float*    Asm  = sm + OF_A;
        float*    rS   = sm + OF_R;
        int*      idxS = (int*)(sm + OF_IDX);
        unsigned* mskS = (unsigned*)(sm + OF_MSK);
        float*    kapF = sm + OF_KF;

        const int b = blockIdx.x;
        const int t0 = c * Cq;

        if (tid < Cq) {
            float4 hv = ((const float4*)g_hd)[(size_t)b * Tq + t0 + tid];
            hv.w = (float)mask[b * Tq + t0 + tid];
            sHd[tid] = hv;
        }
        {
            const float4* gsrc = (const float4*)&g_G[b][c][0][0];
            #pragma unroll 4
            for (int i = tid; i < Cq * Cq / 4; i += 256) {
                float4 v = gsrc[i];
                v.x *= scale; v.y *= scale; v.z *= scale; v.w *= scale;
                ((float4*)sG)[i] = v;
            }
        }
        if (c > 0) {
            const float4* xsrc = (const float4*)&g_Gx[b][c - 1][0][0];
            #pragma unroll 4
            for (int i = tid; i < Cq * Cq / 4; i += 256) {
                float4 v = xsrc[i];
                v.x *= scale; v.y *= scale; v.z *= scale; v.w *= scale;
                ((float4*)sGx)[i] = v;
            }
            if (tid < Sq) Asm[tid] = g_afinC[c - 1][b][tid] * scale;
            if (tid < Cq) {
                kapF[tid] = g_kapC[c - 1][b][tid];
                idxS[tid] = g_idxC[c - 1][b][tid];
            }
        }
        __syncthreads();

        if (c == 0) {
            for (int i = tid; i < Cq * Sq; i += 256) {
                int tau = i >> 6, s = i & 63;
                Qs[tau * 65 + s] = 0.f;
            }
        } else {
            const int t = tid >> 1, hf = (tid & 1) * 32;
            const float* P0r = &g_P0[b][t][0];
            float* Qr = Qs + t * 65;
            #pragma unroll 8
            for (int q = 0; q < 32; ++q) {
                int s = hf + q;
                Qr[s] = Asm[s] * P0r[s];
            }
            const float* gxr = sGx + t * Cq;
            for (int j = 0; j < Cq; ++j) {
                int s = idxS[j];
                if ((unsigned)(s - hf) < 32u)
                    Qr[s] = fmaf(kapF[j], gxr[j], Qr[s]);
            }
        }
        __syncthreads();
        if (tid < Sq) Asm[tid] = 1.f;
        if (tid < Cq) { rS[tid] = 0.f; idxS[tid] = 0; }
        mskS[tid] = 0;
        __syncthreads();

        if (tid < 32) {
            const int l = tid;
            const float wwgg = W_wg[Dq];
            const float bnm = b_nm[0], bwg = b_wg[0];
            float A0 = 1.f, A1 = 1.f;
            float R0 = g_u[b][l], R1 = g_u[b][l + 32];
            float* gE = &g_E[b][c][0][0];
            float* gInv = &g_invA[b][c][0];
            float* gWg  = &g_wgA[b][c][0];
            int*   gMi  = &g_miA[b][c][0];

            for (int t = 0; t < Cq; ++t) {
                const float* gr = sG + t * Cq;
                float g0 = gr[l], g1 = gr[l + 32];
                float g2 = gr[l + 64], g3 = gr[l + 96];

                float s0 = Qs[t * 65 + l];
                float s1 = Qs[t * 65 + l + 32];

                unsigned k0 = okey(s0), k1 = okey(s1);
                unsigned kmx = __reduce_max_sync(0xffffffffu, k0 > k1 ? k0 : k1);
                float mx = dekey(kmx);
                unsigned b0 = __ballot_sync(0xffffffffu, k0 == kmx);
                unsigned b1 = __ballot_sync(0xffffffffu, k1 == kmx);
                int mi = b0 ? (__ffs(b0) - 1) : (__ffs(b1) + 31);

                float e0 = __expf(s0 - mx), e1 = __expf(s1 - mx);
                gE[t * Sq + l] = e0;
                gE[t * Sq + l + 32] = e1;

                int pei = __float2int_rn((e0 + e1) * 16777216.f);
                int pdi = __float2int_rn(fmaf(e0, R0, e1 * R1) * 524288.f);
                pei = __reduce_add_sync(0xffffffffu, pei);
                pdi = __reduce_add_sync(0xffffffffu, pdi);
                float pe = (float)pei * 5.9604645e-8f;
                float pd = (float)pdi * 1.9073486e-6f;

                float inv = __fdividef(1.f, pe);
                float mdot = pd * inv;

                float4 hdt = sHd[t];
                float gg = __fdividef(1.f, 1.f + __expf(-(hdt.x + mdot + bnm)));
                float wg = __fdividef(1.f, 1.f + __expf(-(hdt.z + gg * wwgg + bwg)));
                wg = fminf(wg, 0.2f) * hdt.w;

                if (l == 0) gInv[t] = inv;
                if (l == 1) gWg[t] = wg;
                if (l == 2) gMi[t] = mi;

                float dec = 1.f - wg;
                if (mi == l) {
                    A0 *= dec;
                    R0 = fmaf(dec, R0, wg * hdt.y);
                    Asm[mi] = A0;
                    rS[t] = wg / A0;
                    idxS[t] = mi;
                    mskS[mi * 4 + (t >> 5)] |= 1u << (t & 31);
                } else if (mi == l + 32) {
                    A1 *= dec;
                    R1 = fmaf(dec, R1, wg * hdt.y);
                    Asm[mi] = A1;
                    rS[t] = wg / A1;
                    idxS[t] = mi;
                    mskS[mi * 4 + (t >> 5)] |= 1u << (t & 31);
                }
                {
                    float v;
                    v = Qs[l * 65 + mi];
                    Qs[l * 65 + mi] = fmaf(dec, v, wg * g0);
                    v = Qs[(l + 32) * 65 + mi];
                    Qs[(l + 32) * 65 + mi] = fmaf(dec, v, wg * g1);
                    v = Qs[(l + 64) * 65 + mi];
                    Qs[(l + 64) * 65 + mi] = fmaf(dec, v, wg * g2);
                    v = Qs[(l + 96) * 65 + mi];
                    Qs[(l + 96) * 65 + mi] = fmaf(dec, v, wg * g3);
                }
                __syncwarp();
            }

            g_u[b][l] = R0; g_u[b][l + 32] = R1;
            g_afinC[c][b][l] = A0; g_afinC[c][b][l + 32] = A1;
            #pragma unroll
            for (int q = 0; q < 4; ++q) {
                int j = l + 32 * q;
                int ix = idxS[j];
                g_kapC[c][b][j] = rS[j] * Asm[ix];
                g_idxC[c][b][j] = ix;
            }
        }
        __syncthreads();
        ((unsigned*)&g_mskC[c][b][0][0])[tid] = mskS[tid];
    } else if (blockIdx.x < 136) {
        if (c == 0) return;
        const int id = blockIdx.x - 8;
        const int b = id >> 4, s0 = (id & 15) * 4;

        float*    kap2 = sm;
        float*    af4  = sm + 128;
        unsigned* msk4 = (unsigned*)(sm + 132);
        float*    Bsm  = sm + 160;

        if (tid < Cq) kap2[tid] = g_kapC[c - 1][b][tid];
        if (tid < 4)  af4[tid] = g_afinC[c - 1][b][s0 + tid];
        if (tid < 16) msk4[tid] = ((unsigned*)&g_mskC[c - 1][b][s0][0])[tid];
        __syncthreads();

        const float* Hp = h + ((size_t)b * Tq + (c - 1) * Cq) * Dq;
        if (tid < 224) {
            #pragma unroll
            for (int k = 0; k < 4; ++k) {
                const int s = s0 + k;
                float4 v = ((const float4*)&g_Ball[c - 1][b][s][0])[tid];
                const float as = af4[k];
                v.x *= as; v.y *= as; v.z *= as; v.w *= as;
                #pragma unroll
                for (int w2 = 0; w2 < 4; ++w2) {
                    unsigned wd = msk4[k * 4 + w2];
                    while (wd) {
                        int bp = __ffs(wd) - 1; wd &= wd - 1;
                        int j = w2 * 32 + bp;
                        float kj = kap2[j];
                        float4 hv = ((const float4*)(Hp + (size_t)j * Dq))[tid];
                        v.x = fmaf(kj, hv.x, v.x); v.y = fmaf(kj, hv.y, v.y);
                        v.z = fmaf(kj, hv.z, v.z); v.w = fmaf(kj, hv.w, v.w);
                    }
                }
                ((float4*)&g_Ball[c][b][s][0])[tid] = v;
                ((float4*)&Bsm[k * Dq])[tid] = v;
            }
        }
        __syncthreads();

        if (c < NCq - 1) {
            const int t = tid >> 1, sp = (tid & 1) * 2;
            const float4* Hn = (const float4*)(h + ((size_t)b * Tq + (c + 1) * Cq + t) * Dq);
            const float4* Ba = (const float4*)&Bsm[(sp + 0) * Dq];
            const float4* Bb = (const float4*)&Bsm[(sp + 1) * Dq];
            float a0 = 0.f, a1 = 0.f;
            #pragma unroll 4
            for (int k = 0; k < Dq / 4; ++k) {
                float4 hv = Hn[k];
                float4 x = Ba[k];
                a0 += hv.x * x.x + hv.y * x.y + hv.z * x.z + hv.w * x.w;
                float4 y = Bb[k];
                a1 += hv.x * y.x + hv.y * y.y + hv.z * y.z + hv.w * y.w;
            }
            g_P0[b][t][s0 + sp + 0] = a0;
            g_P0[b][t][s0 + sp + 1] = a1;
        }
    } else if (blockIdx.x < 168) {
        // G[b][c+1] tiles (for the next launch)
        if (c + 1 >= NCq) return;
        const int i = blockIdx.x - 136;
        const int b = i >> 2, tile = i & 3;
        const float* Ar = h + ((size_t)b * Tq + (c + 1) * Cq) * Dq;
        gram_tile32(Ar, Ar, &g_G[b][c + 1][0][0], tile);
    } else if (blockIdx.x < 200) {
        // Gx[b][c] = H_{c+1} H_c^T (for the next launch)
        if (c >= NCq - 1) return;
        const int i = blockIdx.x - 168;
        const int b = i >> 2, tile = i & 3;
        const float* Ar = h + ((size_t)b * Tq + (c + 1) * Cq) * Dq;
        const float* Br = h + ((size_t)b * Tq + c * Cq) * Dq;
        gram_tile32(Ar, Br, &g_Gx[b][c][0][0], tile);
    } else {
        // hd for chunk c+1
        if (c + 1 >= NCq) return;
        const int b = blockIdx.x - 200;
        hd_rows(h + ((size_t)b * Tq + (c + 1) * Cq) * Dq, W_nm, W_wg, b,
                (c + 1) * Cq);
    }
}

// ---------------------------------------------------------------------
__global__ __launch_bounds__(256) void recon_kernel() {
    extern __shared__ float rs[];
    float* sE   = rs + RS_E;
    float* sA   = rs + RS_A;
    float* sr   = rs + RS_R;
    float* sinv = rs + RS_INV;
    float* swg  = rs + RS_WG;
    int*   smi  = (int*)(rs + RS_MI);

    const int b = blockIdx.x >> 5;
    const int c = blockIdx.x & 31;
    const int tid = threadIdx.x;

    const float4* esrc = (const float4*)&g_E[b][c][0][0];
    #pragma unroll 4
    for (int i = tid; i < Cq * Sq / 4; i += 256) ((float4*)sE)[i] = esrc[i];
    if (tid < Cq) {
        sinv[tid] = g_invA[b][c][tid];
        swg[tid]  = g_wgA[b][c][tid];
        smi[tid]  = g_miA[b][c][tid];
    }
    __syncthreads();

    if (tid < Sq) {
        float A = 1.f;
        for (int t = 0; t < Cq; ++t) {
            sA[t * Sq + tid] = A;
            if (smi[t] == tid) {
                A *= (1.f - swg[t]);
                sr[t] = swg[t] / A;
            }
        }
    }
    __syncthreads();

    float* bet = &g_beta[b][c][0][0];
    for (int i = tid; i < Cq * Sq; i += 256) {
        int t = i >> 6;
        bet[i] = sE[i] * sinv[t] * sA[i];
    }
    float* gam = &g_gamma[b][c][0][0];
    for (int i = tid; i < Cq * Cq; i += 256) {
        int t = i >> 7, j = i & 127;
        float gv = 0.f;
        if (j < t) {
            int ix = smi[j];
            gv = sE[t * Sq + ix] * sinv[t] * sr[j] * sA[t * Sq + ix];
        }
        gam[i] = gv;
    }
}

// ---------------------------------------------------------------------
// mbuild: m = [beta|gamma] @ [B_c ; H_c] via tf32 mma
// ---------------------------------------------------------------------
__global__ __launch_bounds__(256) void mbuild_kernel(const float* __restrict__ h)
{
    __shared__ float As[16][132];
    __shared__ float Bs[16][132];

    const int cc = blockIdx.x / 56;
    const int r  = blockIdx.x % 56;
    const int b  = r / 7;
    const int n0 = (r % 7) * 128;
    const int t0 = cc * Cq;
    const int tid = threadIdx.x;
    const int lane = tid & 31;
    const int warp = tid >> 5;
    const int wm = (warp >> 1) * 32;
    const int wn = (warp & 1) * 64;
    const int gr = lane >> 2;
    const int gc = lane & 3;

    const float* Bold = &g_Ball[cc][b][0][0];
    const float* Hc = h + ((size_t)b * Tq + t0) * Dq;
    const float* bet = &g_beta[b][cc][0][0];
    const float* gam = &g_gamma[b][cc][0][0];

    const int lr0 = tid >> 2;
    const int kc  = (tid & 3) * 4;
    const int kr  = tid >> 4;
    const int nc8 = (tid & 15) * 8;

    float acc[2][8][4];
    #pragma unroll
    for (int mt = 0; mt < 2; ++mt)
        #pragma unroll
        for (int nt = 0; nt < 8; ++nt)
            #pragma unroll
            for (int q = 0; q < 4; ++q) acc[mt][nt][q] = 0.f;

    for (int k0 = 0; k0 < Sq + Cq; k0 += 16) {
        float4 a0, a1;
        if (k0 < Sq) {
            a0 = *(const float4*)(bet + lr0 * Sq + k0 + kc);
            a1 = *(const float4*)(bet + (lr0 + 64) * Sq + k0 + kc);
        } else {
            a0 = *(const float4*)(gam + lr0 * Cq + k0 - Sq + kc);
            a1 = *(const float4*)(gam + (lr0 + 64) * Cq + k0 - Sq + kc);
        }
        int kg = k0 + kr;
        const float* rp = (kg < Sq) ? (Bold + (size_t)kg * Dq)
                                    : (Hc + (size_t)(kg - Sq) * Dq);
        float4 b0 = *(const float4*)(rp + n0 + nc8);
        float4 b1 = *(const float4*)(rp + n0 + nc8 + 4);
        __syncthreads();
        As[kc + 0][lr0] = to_tf32(a0.x); As[kc + 1][lr0] = to_tf32(a0.y);
        As[kc + 2][lr0] = to_tf32(a0.z); As[kc + 3][lr0] = to_tf32(a0.w);
        As[kc + 0][lr0 + 64] = to_tf32(a1.x); As[kc + 1][lr0 + 64] = to_tf32(a1.y);
        As[kc + 2][lr0 + 64] = to_tf32(a1.z); As[kc + 3][lr0 + 64] = to_tf32(a1.w);
        Bs[kr][nc8 + 0] = to_tf32(b0.x); Bs[kr][nc8 + 1] = to_tf32(b0.y);
        Bs[kr][nc8 + 2] = to_tf32(b0.z); Bs[kr][nc8 + 3] = to_tf32(b0.w);
        Bs[kr][nc8 + 4] = to_tf32(b1.x); Bs[kr][nc8 + 5] = to_tf32(b1.y);
        Bs[kr][nc8 + 6] = to_tf32(b1.z); Bs[kr][nc8 + 7] = to_tf32(b1.w);
        __syncthreads();
        #pragma unroll
        for (int ks = 0; ks < 16; ks += 8) {
            unsigned afr[2][4];
            #pragma unroll
            for (int mt = 0; mt < 2; ++mt) {
                int row = wm + mt * 16 + gr;
                afr[mt][0] = __float_as_uint(As[ks + gc][row]);
                afr[mt][1] = __float_as_uint(As[ks + gc][row + 8]);
                afr[mt][2] = __float_as_uint(As[ks + gc + 4][row]);
                afr[mt][3] = __float_as_uint(As[ks + gc + 4][row + 8]);
            }
            unsigned bfr[8][2];
            #pragma unroll
            for (int nt = 0; nt < 8; ++nt) {
                int col = wn + nt * 8 + gr;
                bfr[nt][0] = __float_as_uint(Bs[ks + gc][col]);
                bfr[nt][1] = __float_as_uint(Bs[ks + gc + 4][col]);
            }
            #pragma unroll
            for (int mt = 0; mt < 2; ++mt)
                #pragma unroll
                for (int nt = 0; nt < 8; ++nt)
                    MMA_TF32(acc[mt][nt], afr[mt][0], afr[mt][1], afr[mt][2],
                             afr[mt][3], bfr[nt][0], bfr[nt][1]);
        }
    }

    #pragma unroll
    for (int mt = 0; mt < 2; ++mt) {
        #pragma unroll
        for (int nt = 0; nt < 8; ++nt) {
            size_t r0 = (size_t)b * Tq + t0 + wm + mt * 16 + gr;
            size_t r1 = r0 + 8;
            int n = n0 + wn + nt * 8 + 2 * gc;
            g_m[r0 * Dq + n]     = acc[mt][nt][0];
            g_m[r0 * Dq + n + 1] = acc[mt][nt][1];
            g_m[r1 * Dq + n]     = acc[mt][nt][2];
            g_m[r1 * Dq + n + 1] = acc[mt][nt][3];
        }
    }
}

// ---------------------------------------------------------------------
__global__ __launch_bounds__(256) void stats_kernel() {
    int row = blockIdx.x * 8 + (threadIdx.x >> 5);
    int l = threadIdx.x & 31;
    const float* mr = g_m + (size_t)row * Dq;
    float s = 0.f, s2 = 0.f;
    for (int d = l; d < Dq; d += 32) { float v = mr[d]; s += v; s2 += v * v; }
    #pragma unroll
    for (int o = 16; o > 0; o >>= 1) {
        s  += __shfl_xor_sync(0xffffffffu, s, o);
        s2 += __shfl_xor_sync(0xffffffffu, s2, o);
    }
    if (l == 0) {
        float mu = s * (1.f / (float)Dq);
        float var = s2 * (1.f / (float)Dq) - mu * mu;
        g_stats[row][0] = mu;
        g_stats[row][1] = rsqrtf(var + 1e-5f);
    }
}

// ---------------------------------------------------------------------
// final GEMM: tf32 mma.sync, 128x128x16 tiles, LN fused
// ---------------------------------------------------------------------
__global__ __launch_bounds__(256) void gemm_kernel(
    const float* __restrict__ Wt,
    const float* __restrict__ H,
    const float* __restrict__ lng,
    const float* __restrict__ lnb,
    float* __restrict__ C)
{
    __shared__ float As[16][132];
    __shared__ float Bs[16][132];

    const int bm = blockIdx.y * 128;
    const int bn = blockIdx.x * 128;
    const int tid = threadIdx.x;
    const int lane = tid & 31;
    const int warp = tid >> 5;
    const int wm = (warp >> 1) * 32;
    const int wn = (warp & 1) * 64;
    const int gr = lane >> 2;
    const int gc = lane & 3;

    const int lr0 = tid >> 2;
    const int kc  = (tid & 3) * 4;

    const float* Ap0 = g_m + (size_t)(bm + lr0) * GK + kc;
    const float* Ap1 = g_m + (size_t)(bm + lr0 + 64) * GK + kc;
    const float* Bp0 = Wt + (size_t)(bn + lr0) * GK + kc;
    const float* Bp1 = Wt + (size_t)(bn + lr0 + 64) * GK + kc;
    const float mu0 = g_stats[bm + lr0][0],      rs0 = g_stats[bm + lr0][1];
    const float mu1 = g_stats[bm + lr0 + 64][0], rs1 = g_stats[bm + lr0 + 64][1];

    float acc[2][8][4];
    #pragma unroll
    for (int mt = 0; mt < 2; ++mt)
        #pragma unroll
        for (int nt = 0; nt < 8; ++nt)
            #pragma unroll
            for (int q = 0; q < 4; ++q) acc[mt][nt][q] = 0.f;

    float4 pa0 = *(const float4*)(Ap0);
    float4 pa1 = *(const float4*)(Ap1);
    float4 pb0 = *(const float4*)(Bp0);
    float4 pb1 = *(const float4*)(Bp1);

    for (int k0 = 0; k0 < GK; k0 += 16) {
        float4 gv = *(const float4*)(lng + k0 + kc);
        float4 ov = *(const float4*)(lnb + k0 + kc);
        float4 a0 = pa0, a1 = pa1, b0 = pb0, b1 = pb1;
        a0.x = (a0.x - mu0) * rs0 * gv.x + ov.x;
        a0.y = (a0.y - mu0) * rs0 * gv.y + ov.y;
        a0.z = (a0.z - mu0) * rs0 * gv.z + ov.z;
        a0.w = (a0.w - mu0) * rs0 * gv.w + ov.w;
        a1.x = (a1.x - mu1) * rs1 * gv.x + ov.x;
        a1.y = (a1.y - mu1) * rs1 * gv.y + ov.y;
        a1.z = (a1.z - mu1) * rs1 * gv.z + ov.z;
        a1.w = (a1.w - mu1) * rs1 * gv.w + ov.w;
        __syncthreads();
        As[kc + 0][lr0] = to_tf32(a0.x); As[kc + 1][lr0] = to_tf32(a0.y);
        As[kc + 2][lr0] = to_tf32(a0.z); As[kc + 3][lr0] = to_tf32(a0.w);
        As[kc + 0][lr0 + 64] = to_tf32(a1.x); As[kc + 1][lr0 + 64] = to_tf32(a1.y);
        As[kc + 2][lr0 + 64] = to_tf32(a1.z); As[kc + 3][lr0 + 64] = to_tf32(a1.w);
        Bs[kc + 0][lr0] = to_tf32(b0.x); Bs[kc + 1][lr0] = to_tf32(b0.y);
        Bs[kc + 2][lr0] = to_tf32(b0.z); Bs[kc + 3][lr0] = to_tf32(b0.w);
        Bs[kc + 0][lr0 + 64] = to_tf32(b1.x); Bs[kc + 1][lr0 + 64] = to_tf32(b1.y);
        Bs[kc + 2][lr0 + 64] = to_tf32(b1.z); Bs[kc + 3][lr0 + 64] = to_tf32(b1.w);
        __syncthreads();
        if (k0 + 16 < GK) {
            pa0 = *(const float4*)(Ap0 + k0 + 16);
            pa1 = *(const float4*)(Ap1 + k0 + 16);
            pb0 = *(const float4*)(Bp0 + k0 + 16);
            pb1 = *(const float4*)(Bp1 + k0 + 16);
        }
        #pragma unroll
        for (int ks = 0; ks < 16; ks += 8) {
            unsigned afr[2][4];
            #pragma unroll
            for (int mt = 0; mt < 2; ++mt) {
                int row = wm + mt * 16 + gr;
                afr[mt][0] = __float_as_uint(As[ks + gc][row]);
                afr[mt][1] = __float_as_uint(As[ks + gc][row + 8]);
                afr[mt][2] = __float_as_uint(As[ks + gc + 4][row]);
                afr[mt][3] = __float_as_uint(As[ks + gc + 4][row + 8]);
            }
            unsigned bfr[8][2];
            #pragma unroll
            for (int nt = 0; nt < 8; ++nt) {
                int col = wn + nt * 8 + gr;
                bfr[nt][0] = __float_as_uint(Bs[ks + gc][col]);
                bfr[nt][1] = __float_as_uint(Bs[ks + gc + 4][col]);
            }
            #pragma unroll
            for (int mt = 0; mt < 2; ++mt)
                #pragma unroll
                for (int nt = 0; nt < 8; ++nt)
                    MMA_TF32(acc[mt][nt], afr[mt][0], afr[mt][1], afr[mt][2],
                             afr[mt][3], bfr[nt][0], bfr[nt][1]);
        }
    }

    #pragma unroll
    for (int mt = 0; mt < 2; ++mt) {
        #pragma unroll
        for (int nt = 0; nt < 8; ++nt) {
            size_t r0 = (size_t)bm + wm + mt * 16 + gr;
            size_t r1 = r0 + 8;
            int n = bn + wn + nt * 8 + 2 * gc;
            float d0 = fminf(fmaxf(acc[mt][nt][0] * 0.5f, -2.f), 2.f);
            float d1 = fminf(fmaxf(acc[mt][nt][1] * 0.5f, -2.f), 2.f);
            float d2 = fminf(fmaxf(acc[mt][nt][2] * 0.5f, -2.f), 2.f);
            float d3 = fminf(fmaxf(acc[mt][nt][3] * 0.5f, -2.f), 2.f);
            C[r0 * GN + n]     = H[r0 * GN + n]     + d0;
            C[r0 * GN + n + 1] = H[r0 * GN + n + 1] + d1;
            C[r1 * GN + n]     = H[r1 * GN + n]     + d2;
            C[r1 * GN + n + 1] = H[r1 * GN + n + 1] + d3;
        }
    }
}

// ---------------------------------------------------------------------
extern "C" void kernel_launch(void* const* d_in, const int* in_sizes, int n_in,
                              void* d_out, int out_size) {
    const float* h    = (const float*)d_in[0];
    const int*   mask = (const int*)  d_in[1];
    const float* lng  = (const float*)d_in[2];
    const float* lnb  = (const float*)d_in[3];
    const float* Wout = (const float*)d_in[4];
    const float* Wnm  = (const float*)d_in[5];
    const float* bnm  = (const float*)d_in[6];
    const float* Wwg  = (const float*)d_in[7];
    const float* bwg  = (const float*)d_in[8];
    float* out = (float*)d_out;

    cudaFuncSetAttribute(chunk_kernel,
                         cudaFuncAttributeMaxDynamicSharedMemorySize,
                         SMEM_BYTES);
    cudaFuncSetAttribute(recon_kernel,
                         cudaFuncAttributeMaxDynamicSharedMemorySize,
                         RSMEM_BYTES);

    init_kernel<<<448, 256>>>();
    pre0_kernel<<<40, 256>>>(h, Wnm, Wwg);

    for (int c = 0; c < NCq; ++c)
        chunk_kernel<<<208, 256, SMEM_BYTES>>>(h, mask, bnm, Wnm, Wwg, bwg, c);

    recon_kernel<<<Bq * NCq, 256, RSMEM_BYTES>>>();
    mbuild_kernel<<<NCq * 56, 256>>>(h);
    stats_kernel<<<GM / 8, 256>>>();

    dim3 grid(GN / 128, GM / 128);
    gemm_kernel<<<grid, 256>>>(Wout, h, lng, lnb, out);
}